// round 14
// baseline (speedup 1.0000x reference)
#include <cuda_runtime.h>
#include <cuda_bf16.h>
#include <cuda_fp16.h>
#include <math.h>
#include <float.h>
#include <stdint.h>

#define BSZ 8
#define N0 2048
#define N1 512
#define N2 128

// Split-fp16 head GEMMs (mma.sync; K doubled, A'=[hi|lo], B'=[hi|hi]):
//   gemm1: M=16384, N=1024, K'=2944; gemm2: N=512, K'=2048; gemm3: N=128(pad 50), K'=1024

// ---- scratch (device globals; allocations are forbidden) ----
__device__ int   g_perm1[N0];
__device__ int   g_perm2[N1];
__device__ int   g_ni0[BSZ*N0*32];
__device__ float g_dn0[BSZ*N0*32*3];
__device__ float g_fmA[BSZ*N0*96];
__device__ float g_ft [BSZ*N0*64];
__device__ float g_v1 [BSZ*N1*3];
__device__ int   g_ni1[BSZ*N1*32];
__device__ float g_dn1[BSZ*N1*32*3];
__device__ float g_fmB[BSZ*N1*192];
__device__ float g_v2 [BSZ*N2*3];
__device__ int   g_ni2[BSZ*N2*32];
__device__ float g_dn2[BSZ*N2*32*3];
__device__ float g_fmC[BSZ*N2*256];
__device__ float g_fglob[BSZ*256];
__device__ int   g_n1[BSZ*N0];
__device__ int   g_n2[BSZ*N0];

__device__ __half g_A1[(size_t)16384*2944];
__device__ __half g_W1[(size_t)1024 *2944];
__device__ __half g_A2[(size_t)16384*2048];
__device__ __half g_W2[(size_t)512  *2048];
__device__ __half g_A3[(size_t)16384*1024];
__device__ __half g_W3[(size_t)128  *1024];

__device__ __forceinline__ uint32_t smem_u32(const void* p){
  uint32_t a;
  asm("{ .reg .u64 t; cvta.to.shared.u64 t, %1; cvt.u32.u64 %0, t; }" : "=r"(a) : "l"(p));
  return a;
}
__device__ __forceinline__ void split_f16(float v, __half& hi, __half& lo){
  hi = __float2half_rn(v);
  lo = __float2half_rn(v - __half2float(hi));
}
__device__ __forceinline__ unsigned packh(__half a, __half b){
  return (unsigned)__half_as_ushort(a) | ((unsigned)__half_as_ushort(b) << 16);
}

// ---- threefry2x32 (exact JAX cipher) ----
__device__ __forceinline__ void tfry(unsigned k0, unsigned k1, unsigned &x0, unsigned &x1){
  unsigned ks2 = k0 ^ k1 ^ 0x1BD11BDAu;
  x0 += k0; x1 += k1;
#define TF_R(r) { x0 += x1; x1 = (x1<<(r))|(x1>>(32-(r))); x1 ^= x0; }
  TF_R(13) TF_R(15) TF_R(26) TF_R(6)   x0 += k1;  x1 += ks2 + 1u;
  TF_R(17) TF_R(29) TF_R(16) TF_R(24)  x0 += ks2; x1 += k0  + 2u;
  TF_R(13) TF_R(15) TF_R(26) TF_R(6)   x0 += k0;  x1 += k1  + 3u;
  TF_R(17) TF_R(29) TF_R(16) TF_R(24)  x0 += k1;  x1 += ks2 + 4u;
  TF_R(13) TF_R(15) TF_R(26) TF_R(6)   x0 += ks2; x1 += k0  + 5u;
#undef TF_R
}
__device__ __forceinline__ void tfry2(unsigned k0, unsigned k1, unsigned c0, unsigned c1,
                                      unsigned &o0, unsigned &o1){
  o0 = c0; o1 = c1; tfry(k0, k1, o0, o1);
}

__device__ void bitonic_sort(unsigned long long* sk, int* sv, int n, int tid, int nthr){
  for (int k=2;k<=n;k<<=1){
    for (int j=k>>1;j>0;j>>=1){
      for (int i=tid;i<n;i+=nthr){
        int ix=i^j;
        if (ix>i){
          bool up = ((i & k)==0);
          unsigned long long a=sk[i], c=sk[ix];
          if ((a>c)==up){
            sk[i]=c; sk[ix]=a;
            int t=sv[i]; sv[i]=sv[ix]; sv[ix]=t;
          }
        }
      }
      __syncthreads();
    }
  }
}

// jax.random.permutation, PARTITIONABLE threefry (modern JAX default)
__global__ void k_perm(){
  __shared__ unsigned long long sk[2048];
  __shared__ int sv[2048];
  int tid = threadIdx.x;   // 1024

  unsigned ck0, ck1; tfry2(0u, 42u, 0u, 1u, ck0, ck1);   // fold_in(key(42),1)
  for (int round=0; round<2; round++){
    unsigned nk0, nk1; tfry2(ck0, ck1, 0u, 0u, nk0, nk1);
    unsigned s0,  s1;  tfry2(ck0, ck1, 0u, 1u, s0,  s1);
    unsigned a0,a1; tfry2(s0, s1, 0u, (unsigned)tid,        a0, a1);
    unsigned b0,b1; tfry2(s0, s1, 0u, (unsigned)(tid+1024), b0, b1);
    unsigned bitsA = a0 ^ a1, bitsB = b0 ^ b1;
    if (round==0){ sv[tid]=tid; sv[tid+1024]=tid+1024; }
    __syncthreads();
    sk[tid]      = ((unsigned long long)bitsA<<32) | (unsigned)tid;
    sk[tid+1024] = ((unsigned long long)bitsB<<32) | (unsigned)(tid+1024);
    __syncthreads();
    bitonic_sort(sk, sv, 2048, tid, 1024);
    ck0=nk0; ck1=nk1;
  }
  g_perm1[tid]      = sv[tid];
  g_perm1[tid+1024] = sv[tid+1024];
  __syncthreads();

  unsigned f0, f1; tfry2(0u, 42u, 0u, 2u, f0, f1);        // fold_in(key(42),2)
  unsigned s0, s1; tfry2(f0, f1, 0u, 1u, s0, s1);
  if (tid < 512){
    unsigned a0,a1; tfry2(s0, s1, 0u, (unsigned)tid, a0, a1);
    sk[tid] = ((unsigned long long)(a0^a1)<<32) | (unsigned)tid;
    sv[tid] = tid;
  }
  __syncthreads();
  bitonic_sort(sk, sv, 512, tid, 1024);
  if (tid<512) g_perm2[tid]=sv[tid];
}

// ---- ball query ----
__global__ void k_ball(const float* __restrict__ verts, int Nv, float r2,
                       int* __restrict__ ni, float* __restrict__ dn){
  __shared__ int sidx[4][32];
  int b = blockIdx.y;
  int w = threadIdx.x>>5, lane = threadIdx.x&31;
  int v = blockIdx.x*4 + w;
  const float* vb = verts + (size_t)b*Nv*3;
  float cx = vb[v*3+0], cy = vb[v*3+1], cz = vb[v*3+2];
  int cnt = 0;
  for (int base=0; base<Nv && cnt<32; base+=32){
    int j = base + lane;
    float dx = __fsub_rn(cx, vb[j*3+0]);
    float dy = __fsub_rn(cy, vb[j*3+1]);
    float dz = __fsub_rn(cz, vb[j*3+2]);
    float sq = __fadd_rn(__fadd_rn(__fmul_rn(dx,dx),__fmul_rn(dy,dy)),__fmul_rn(dz,dz));
    unsigned m = __ballot_sync(0xffffffffu, !(sq > r2));
    while (m && cnt<32){
      int l = __ffs(m)-1; m &= m-1u;
      if (lane==0) sidx[w][cnt] = base + l;
      cnt++;
    }
  }
  __syncwarp();
  int first = sidx[w][0];
  int idx = (lane<cnt) ? sidx[w][lane] : first;
  ni[((size_t)(b*Nv)+v)*32 + lane] = idx;
  float nx = __fsub_rn(vb[idx*3+0], cx);
  float ny = __fsub_rn(vb[idx*3+1], cy);
  float nz = __fsub_rn(vb[idx*3+2], cz);
  float nrm = sqrtf(nx*nx + ny*ny + nz*nz);
  float den = fmaxf(nrm, 1e-12f);
  float* dp = dn + (((size_t)(b*Nv)+v)*32 + lane)*3;
  dp[0]=nx/den; dp[1]=ny/den; dp[2]=nz/den;
}

__global__ void k_surface(const float* __restrict__ dn, const float* __restrict__ d,
                          float* __restrict__ fmOut, int ldOut, int Nv){
  int b = blockIdx.y;
  int w = threadIdx.x>>5, lane = threadIdx.x&31;
  int v = blockIdx.x*8 + w;
  float u0=d[lane], u1=d[32+lane], u2=d[64+lane];
  float den = fmaxf(sqrtf(u0*u0+u1*u1+u2*u2), 1e-12f);
  u0/=den; u1/=den; u2/=den;
  const float* dp = dn + ((size_t)(b*Nv)+v)*96;
  float m = 0.f;
  #pragma unroll 4
  for (int n=0;n<32;n++){
    float t = dp[n*3+0]*u0 + dp[n*3+1]*u1 + dp[n*3+2]*u2;
    m = fmaxf(m, t);
  }
  fmOut[((size_t)(b*Nv)+v)*ldOut + lane] = m;
}

// ---- linear: 32 vertices/block, w + features staged in dynamic smem ----
// Each thread computes 8 contiguous outputs for one vertex; accumulation
// order per output identical to reference (ascending c, single acc).
__global__ void k_linear(const float* __restrict__ fm, int ld, int Cin,
                         const float* __restrict__ w, const float* __restrict__ bias,
                         float* __restrict__ ft, int Nv){
  extern __shared__ float smw[];           // [Cin*64] weights, then [32*Cin] features
  float* sfm = smw + Cin*64;
  int b = blockIdx.y;
  int v0 = blockIdx.x*32;
  int tid = threadIdx.x;   // 256
  for (int i=tid; i<Cin*64; i+=256) smw[i] = w[i];
  for (int i=tid; i<32*Cin; i+=256){
    int vl = i / Cin, c = i - vl*Cin;
    sfm[vl*Cin + c] = fm[((size_t)(b*Nv) + v0+vl)*ld + c];
  }
  __syncthreads();
  int vl = tid >> 3;          // 0..31
  int o0 = (tid & 7) * 8;     // 0..56
  float acc[8];
  #pragma unroll
  for (int q=0;q<8;q++) acc[q] = bias[o0+q];
  const float* fv = sfm + vl*Cin;
  for (int c=0;c<Cin;c++){
    float x = fv[c];
    #pragma unroll
    for (int q=0;q<8;q++) acc[q] += x * smw[c*64 + o0 + q];
  }
  float* op = ft + ((size_t)(b*Nv) + v0+vl)*64 + o0;
  #pragma unroll
  for (int q=0;q<8;q++) op[q] = acc[q];
}

__global__ void k_act(const float* __restrict__ dn, const int* __restrict__ ni,
                      const float* __restrict__ dd, const float* __restrict__ ft,
                      float* __restrict__ fmOut, int ldOut, int Coff, int Nv){
  int b = blockIdx.y;
  int w = threadIdx.x>>5, lane = threadIdx.x&31;
  int v = blockIdx.x*8 + w;
  float u0=dd[lane], u1=dd[32+lane], u2=dd[64+lane];
  float den = fmaxf(sqrtf(u0*u0+u1*u1+u2*u2), 1e-12f);
  u0/=den; u1/=den; u2/=den;
  const float* dp  = dn + ((size_t)(b*Nv)+v)*96;
  const int*   nip = ni + ((size_t)(b*Nv)+v)*32;
  const float* ftb = ft + (size_t)b*Nv*64;
  float center = ftb[(size_t)v*64 + lane];
  float act = -FLT_MAX;
  for (int n=0;n<32;n++){
    int nb = nip[n];
    float t = fmaxf(dp[n*3+0]*u0 + dp[n*3+1]*u1 + dp[n*3+2]*u2, 0.f);
    float s = ftb[(size_t)nb*64 + 32 + lane];
    act = fmaxf(act, t*s);
  }
  fmOut[((size_t)(b*Nv)+v)*ldOut + Coff + lane] = fmaxf(center + act, 0.f);
}

__global__ void k_pool(const int* __restrict__ perm, const int* __restrict__ ni,
                       const float* __restrict__ fmIn, int ldIn, int C,
                       const float* __restrict__ vin, float* __restrict__ fmOut, int ldOut,
                       float* __restrict__ vout, int Nin, int Nout){
  int b = blockIdx.y, p = blockIdx.x;
  int v = perm[p];
  const int* nip = ni + ((size_t)(b*Nin)+v)*32;
  int j0=nip[0], j1=nip[1], j2=nip[2], j3=nip[3];
  const float* base = fmIn + (size_t)b*Nin*ldIn;
  for (int c=threadIdx.x; c<C; c+=blockDim.x){
    float m = fmaxf(fmaxf(base[(size_t)j0*ldIn+c], base[(size_t)j1*ldIn+c]),
                    fmaxf(base[(size_t)j2*ldIn+c], base[(size_t)j3*ldIn+c]));
    fmOut[((size_t)(b*Nout)+p)*ldOut + c] = m;
  }
  if (threadIdx.x<3)
    vout[((size_t)(b*Nout)+p)*3+threadIdx.x] = vin[((size_t)(b*Nin)+v)*3+threadIdx.x];
}

__global__ void k_global(const float* __restrict__ fmC, float* __restrict__ fg){
  int b = blockIdx.x, c = threadIdx.x;
  float m = -FLT_MAX;
  for (int v=0; v<N2; v++) m = fmaxf(m, fmC[((size_t)(b*N2)+v)*256 + c]);
  fg[b*256+c] = m;
}

__global__ void k_nearest(const float* __restrict__ q, const float* __restrict__ src,
                          int Nsrc, int* __restrict__ out){
  int b = blockIdx.y;
  int w = threadIdx.x>>5, lane = threadIdx.x&31;
  int v = blockIdx.x*4 + w;
  const float* qp = q + ((size_t)(b*N0)+v)*3;
  float qx=qp[0], qy=qp[1], qz=qp[2];
  float best = FLT_MAX; int bi = 0x7fffffff;
  for (int j=lane; j<Nsrc; j+=32){
    const float* s = src + ((size_t)(b*Nsrc)+j)*3;
    float dx=__fsub_rn(qx,s[0]), dy=__fsub_rn(qy,s[1]), dz=__fsub_rn(qz,s[2]);
    float sq=__fadd_rn(__fadd_rn(__fmul_rn(dx,dx),__fmul_rn(dy,dy)),__fmul_rn(dz,dz));
    if (sq < best){ best=sq; bi=j; }
  }
  for (int off=16; off; off>>=1){
    float ob = __shfl_down_sync(0xffffffffu, best, off);
    int   oi = __shfl_down_sync(0xffffffffu, bi,   off);
    if (ob < best || (ob==best && oi<bi)){ best=ob; bi=oi; }
  }
  if (lane==0) out[(size_t)b*N0+v] = bi;
}

// ---- fuse -> split-fp16 A1 [16384][2944] = [hi(1472)|lo]; packed 4B stores ----
__device__ __forceinline__ float fuse_fetch(int c, const float* fa, const float* fb,
                                            const float* fc, const float* fg,
                                            const float* onehot, int b){
  if (c>=1424) return 0.f;
  if      (c<32)   return fa[c];
  else if (c<96)   return fa[c-32];
  else if (c<192)  return fa[c-96];
  else if (c<320)  return fb[c-192];
  else if (c<480)  return fb[c-320];
  else if (c<672)  return fb[c-480];
  else if (c<896)  return fc[c-672];
  else if (c<1152) return fc[c-896];
  else if (c<1408) return fg[b*256 + (c-1152)];
  else             return onehot[b*16 + (c-1408)];
}

__global__ void k_fuse_split(const float* __restrict__ onehot, const float* __restrict__ fmA,
                             const float* __restrict__ fmB, const float* __restrict__ fmC,
                             const float* __restrict__ fg, const int* __restrict__ n1,
                             const int* __restrict__ n2, __half* __restrict__ A1){
  int b = blockIdx.y, v = blockIdx.x;
  int i1 = n1[b*N0+v], i2 = n2[b*N0+v];
  const float* fa = fmA + ((size_t)(b*N0)+v )*96;
  const float* fb = fmB + ((size_t)(b*N1)+i1)*192;
  const float* fc = fmC + ((size_t)(b*N2)+i2)*256;
  size_t row = (size_t)(b*N0 + v) * 2944;
  for (int c2=threadIdx.x; c2<736; c2+=256){
    int c = c2*2;
    float x0 = fuse_fetch(c,   fa, fb, fc, fg, onehot, b);
    float x1 = fuse_fetch(c+1, fa, fb, fc, fg, onehot, b);
    __half h0,l0,h1,l1;
    split_f16(x0,h0,l0); split_f16(x1,h1,l1);
    *(unsigned*)&A1[row + c]        = packh(h0,h1);
    *(unsigned*)&A1[row + 1472 + c] = packh(l0,l1);
  }
}

// ---- weight -> split-fp16 row-major [Npad][2*Kpad] = [hi | hi]; zero-pads ----
__global__ void k_wsplit(const float* __restrict__ w, int N, int K, int Kpad,
                         __half* __restrict__ out, int total){
  int idx = blockIdx.x*256 + threadIdx.x;
  if (idx >= total) return;
  int n = idx / Kpad, c = idx - n*Kpad;
  float v = (n < N && c < K) ? w[(size_t)n*K + c] : 0.f;
  __half hi = __float2half_rn(v);
  size_t base = (size_t)n * 2 * Kpad;
  out[base + c]        = hi;
  out[base + Kpad + c] = hi;
}

// ---- fp16 mma.sync GEMM (R13 baseline): BM=BN=128, BK=64, 2-stage, 2 CTAs/SM ----
#define MM_STG 2
__global__ void __launch_bounds__(256, 2)
k_mm(const __half* __restrict__ A, const __half* __restrict__ B,
     const float* __restrict__ bias, int K,
     __half* __restrict__ Anext, int Knext,
     float* __restrict__ Cfinal, int Nfinal)
{
  extern __shared__ char sm[];
  int tid = threadIdx.x, lane = tid&31, wid = tid>>5;
  int bn = blockIdx.x*128, bm = blockIdx.y*128;
  int wm = (wid>>2)*64, wn = (wid&3)*32;
  int nK = K >> 6;
  uint32_t sA0 = smem_u32(sm);
  uint32_t sB0 = sA0 + MM_STG*16384;

  float acc[4][4][4];
  #pragma unroll
  for (int i=0;i<4;i++)
    #pragma unroll
    for (int j=0;j<4;j++)
      #pragma unroll
      for (int q=0;q<4;q++) acc[i][j][q]=0.f;

  #define MM_ISSUE(KT) do{ \
    int _s = (KT) % MM_STG; \
    _Pragma("unroll") \
    for (int it=0; it<4; it++){ \
      int idx = it*256 + tid; \
      int r = idx>>3, c = idx&7; \
      uint32_t sw = ((uint32_t)(c ^ (r&7)))<<4; \
      uint32_t sa = sA0 + _s*16384 + r*128 + sw; \
      const void* ga = A + (size_t)(bm+r)*K + (KT)*64 + c*8; \
      asm volatile("cp.async.cg.shared.global [%0], [%1], 16;" :: "r"(sa), "l"(ga)); \
      uint32_t sb = sB0 + _s*16384 + r*128 + sw; \
      const void* gb = B + (size_t)(bn+r)*K + (KT)*64 + c*8; \
      asm volatile("cp.async.cg.shared.global [%0], [%1], 16;" :: "r"(sb), "l"(gb)); \
    } \
    asm volatile("cp.async.commit_group;" ::: "memory"); \
  } while(0)

  MM_ISSUE(0);

  for (int kt=0; kt<nK; kt++){
    int s = kt % MM_STG;
    asm volatile("cp.async.wait_group 0;" ::: "memory");
    __syncthreads();
    if (kt+1 < nK) MM_ISSUE(kt+1);
    uint32_t ab = sA0 + s*16384;
    uint32_t bb = sB0 + s*16384;
    #pragma unroll
    for (int kk=0; kk<4; kk++){
      uint32_t af[4][4], bfr[2][4];
      #pragma unroll
      for (int fm=0; fm<4; fm++){
        int row = wm + fm*16 + (lane&15);
        int ch  = kk*2 + (lane>>4);
        uint32_t ad = ab + row*128 + ((uint32_t)(ch ^ (row&7))<<4);
        asm volatile("ldmatrix.sync.aligned.m8n8.x4.shared.b16 {%0,%1,%2,%3}, [%4];"
          : "=r"(af[fm][0]),"=r"(af[fm][1]),"=r"(af[fm][2]),"=r"(af[fm][3]) : "r"(ad));
      }
      #pragma unroll
      for (int fp=0; fp<2; fp++){
        int row = wn + fp*16 + ((lane>>4)&1)*8 + (lane&7);
        int ch  = kk*2 + ((lane>>3)&1);
        uint32_t bd = bb + row*128 + ((uint32_t)(ch ^ (row&7))<<4);
        asm volatile("ldmatrix.sync.aligned.m8n8.x4.shared.b16 {%0,%1,%2,%3}, [%4];"
          : "=r"(bfr[fp][0]),"=r"(bfr[fp][1]),"=r"(bfr[fp][2]),"=r"(bfr[fp][3]) : "r"(bd));
      }
      #pragma unroll
      for (int fm=0; fm<4; fm++)
        #pragma unroll
        for (int fn=0; fn<4; fn++){
          uint32_t b0 = bfr[fn>>1][(fn&1)*2], b1 = bfr[fn>>1][(fn&1)*2+1];
          asm volatile("mma.sync.aligned.m16n8k16.row.col.f32.f16.f16.f32 "
            "{%0,%1,%2,%3}, {%4,%5,%6,%7}, {%8,%9}, {%0,%1,%2,%3};"
            : "+f"(acc[fm][fn][0]), "+f"(acc[fm][fn][1]), "+f"(acc[fm][fn][2]), "+f"(acc[fm][fn][3])
            : "r"(af[fm][0]), "r"(af[fm][1]), "r"(af[fm][2]), "r"(af[fm][3]), "r"(b0), "r"(b1));
        }
    }
    __syncthreads();
  }

  if (Anext){
    #pragma unroll
    for (int fm=0; fm<4; fm++){
      #pragma unroll
      for (int fn=0; fn<4; fn++){
        int r0 = wm + fm*16 + (lane>>2);
        int c0 = wn + fn*8 + (lane&3)*2;
        float b0 = bias[bn + c0], b1 = bias[bn + c0 + 1];
        #pragma unroll
        for (int h=0; h<2; h++){
          int r = r0 + h*8;
          float v0 = fmaxf(acc[fm][fn][h*2+0] + b0, 0.f);
          float v1 = fmaxf(acc[fm][fn][h*2+1] + b1, 0.f);
          __half h0,l0,h1,l1;
          split_f16(v0,h0,l0); split_f16(v1,h1,l1);
          *(unsigned*)(sm + r*256 + c0*2)         = packh(h0,h1);
          *(unsigned*)(sm + 32768 + r*256 + c0*2) = packh(l0,l1);
        }
      }
    }
    __syncthreads();
    size_t rstride = 2*(size_t)Knext;
    #pragma unroll
    for (int seg=0; seg<2; seg++){
      int srcoff = seg*32768;
      size_t segoff = (size_t)seg*Knext;
      #pragma unroll
      for (int p=0; p<8; p++){
        int idx = p*256 + tid;
        int r = idx>>4, cb = (idx&15)*16;
        uint4 val = *(const uint4*)(sm + srcoff + r*256 + cb);
        *(uint4*)((char*)(Anext + (size_t)(bm+r)*rstride + segoff + bn) + cb) = val;
      }
    }
  } else {
    #pragma unroll
    for (int fm=0; fm<4; fm++){
      #pragma unroll
      for (int fn=0; fn<4; fn++){
        int r0 = wm + fm*16 + (lane>>2);
        int c0 = wn + fn*8 + (lane&3)*2;
        #pragma unroll
        for (int h=0; h<2; h++){
          int m = bm + r0 + h*8;
          int n0g = bn + c0;
          if (n0g   < Nfinal) Cfinal[(size_t)m*Nfinal + n0g  ] = acc[fm][fn][h*2+0] + bias[n0g];
          if (n0g+1 < Nfinal) Cfinal[(size_t)m*Nfinal + n0g+1] = acc[fm][fn][h*2+1] + bias[n0g+1];
        }
      }
    }
  }
  #undef MM_ISSUE
}

// ---- host launch ----
static void* sym_addr_(const void* s){ void* p=nullptr; cudaGetSymbolAddress(&p, s); return p; }

extern "C" void kernel_launch(void* const* d_in, const int* in_sizes, int n_in,
                              void* d_out, int out_size){
  const float* vertices = (const float*)d_in[0];
  const float* onehot   = (const float*)d_in[1];
  const float* d0       = (const float*)d_in[2];
  const float* W[8]; const float* Bb[8]; const float* DD[8];
  for (int i=1;i<=7;i++){
    W[i]  = (const float*)d_in[3*i];
    Bb[i] = (const float*)d_in[3*i+1];
    DD[i] = (const float*)d_in[3*i+2];
  }
  const float* cw1=(const float*)d_in[24]; const float* cb1=(const float*)d_in[25];
  const float* cw2=(const float*)d_in[26]; const float* cb2=(const float*)d_in[27];
  const float* cw3=(const float*)d_in[28]; const float* cb3=(const float*)d_in[29];
  float* out = (float*)d_out;

  int*   perm1=(int*)  sym_addr_(g_perm1); int*   perm2=(int*)  sym_addr_(g_perm2);
  int*   ni0  =(int*)  sym_addr_(g_ni0);   float* dn0  =(float*)sym_addr_(g_dn0);
  float* fmA  =(float*)sym_addr_(g_fmA);   float* ft   =(float*)sym_addr_(g_ft);
  float* v1   =(float*)sym_addr_(g_v1);
  int*   ni1  =(int*)  sym_addr_(g_ni1);   float* dn1  =(float*)sym_addr_(g_dn1);
  float* fmB  =(float*)sym_addr_(g_fmB);   float* v2   =(float*)sym_addr_(g_v2);
  int*   ni2  =(int*)  sym_addr_(g_ni2);   float* dn2  =(float*)sym_addr_(g_dn2);
  float* fmC  =(float*)sym_addr_(g_fmC);   float* fg   =(float*)sym_addr_(g_fglob);
  int*   n1   =(int*)  sym_addr_(g_n1);    int*   n2   =(int*)  sym_addr_(g_n2);
  __half* A1=(__half*)sym_addr_(g_A1);  __half* W1=(__half*)sym_addr_(g_W1);
  __half* A2=(__half*)sym_addr_(g_A2);  __half* W2=(__half*)sym_addr_(g_W2);
  __half* A3=(__half*)sym_addr_(g_A3);  __half* W3=(__half*)sym_addr_(g_W3);

  const float R2A = (float)(0.25*0.25);
  const float R2B = (float)(0.39*0.39);
  const float R2C = (float)(0.63*0.63);

  const int DSMEM = MM_STG*16384*2;   // 64KB
  cudaFuncSetAttribute(k_mm, cudaFuncAttributeMaxDynamicSharedMemorySize, DSMEM);
  cudaFuncSetAttribute(k_linear, cudaFuncAttributeMaxDynamicSharedMemorySize, 224*96*4);

  k_perm<<<1,1024>>>();

  // Stage A (2048 pts)
  k_ball   <<<dim3(N0/4,BSZ),128>>>(vertices, N0, R2A, ni0, dn0);
  k_surface<<<dim3(N0/8,BSZ),256>>>(dn0, d0, fmA, 96, N0);
  k_linear <<<dim3(N0/32,BSZ),256, 32*96*4>>>(fmA, 96, 32,  W[1], Bb[1], ft, N0);
  k_act    <<<dim3(N0/8,BSZ),256>>>(dn0, ni0, DD[1], ft, fmA, 96, 32, N0);
  k_linear <<<dim3(N0/32,BSZ),256, 64*96*4>>>(fmA, 96, 64,  W[2], Bb[2], ft, N0);
  k_act    <<<dim3(N0/8,BSZ),256>>>(dn0, ni0, DD[2], ft, fmA, 96, 64, N0);
  k_pool   <<<dim3(N1,BSZ),128>>>(perm1, ni0, fmA, 96, 96, vertices, fmB, 192, v1, N0, N1);

  // Stage B (512 pts)
  k_ball   <<<dim3(N1/4,BSZ),128>>>(v1, N1, R2B, ni1, dn1);
  k_linear <<<dim3(N1/32,BSZ),256, 96*96*4>>>(fmB, 192, 96,  W[3], Bb[3], ft, N1);
  k_act    <<<dim3(N1/8,BSZ),256>>>(dn1, ni1, DD[3], ft, fmB, 192, 96, N1);
  k_linear <<<dim3(N1/32,BSZ),256, 128*96*4>>>(fmB, 192, 128, W[4], Bb[4], ft, N1);
  k_act    <<<dim3(N1/8,BSZ),256>>>(dn1, ni1, DD[4], ft, fmB, 192, 128, N1);
  k_linear <<<dim3(N1/32,BSZ),256, 160*96*4>>>(fmB, 192, 160, W[5], Bb[5], ft, N1);
  k_act    <<<dim3(N1/8,BSZ),256>>>(dn1, ni1, DD[5], ft, fmB, 192, 160, N1);
  k_pool   <<<dim3(N2,BSZ),128>>>(perm2, ni1, fmB, 192, 192, v1, fmC, 256, v2, N1, N2);

  // Stage C (128 pts)
  k_ball   <<<dim3(N2/4,BSZ),128>>>(v2, N2, R2C, ni2, dn2);
  k_linear <<<dim3(N2/32,BSZ),256, 192*96*4>>>(fmC, 256, 192, W[6], Bb[6], ft, N2);
  k_act    <<<dim3(N2/8,BSZ),256>>>(dn2, ni2, DD[6], ft, fmC, 256, 192, N2);
  k_linear <<<dim3(N2/32,BSZ),256, 224*96*4>>>(fmC, 256, 224, W[7], Bb[7], ft, N2);
  k_act    <<<dim3(N2/8,BSZ),256>>>(dn2, ni2, DD[7], ft, fmC, 256, 224, N2);
  k_global <<<BSZ,256>>>(fmC, fg);

  // Fuse + head (split-fp16 mma.sync)
  k_nearest<<<dim3(N0/4,BSZ),128>>>(vertices, v1, N1, n1);
  k_nearest<<<dim3(N0/4,BSZ),128>>>(vertices, v2, N2, n2);
  k_wsplit <<<(1024*1472+255)/256,256>>>(cw1, 1024, 1424, 1472, W1, 1024*1472);
  k_wsplit <<<( 512*1024+255)/256,256>>>(cw2,  512, 1024, 1024, W2,  512*1024);
  k_wsplit <<<( 128* 512+255)/256,256>>>(cw3,   50,  512,  512, W3,  128* 512);
  k_fuse_split<<<dim3(N0,BSZ),256>>>(onehot, fmA, fmB, fmC, fg, n1, n2, A1);
  k_mm<<<dim3(8,128),256,DSMEM>>>(A1, W1, cb1, 2944, A2, 1024, nullptr, 0);
  k_mm<<<dim3(4,128),256,DSMEM>>>(A2, W2, cb2, 2048, A3,  512, nullptr, 0);
  k_mm<<<dim3(1,128),256,DSMEM>>>(A3, W3, cb3, 1024, nullptr, 0, out, 50);
}

// round 15
// speedup vs baseline: 1.0771x; 1.0771x over previous
#include <cuda_runtime.h>
#include <cuda_bf16.h>
#include <cuda_fp16.h>
#include <math.h>
#include <float.h>
#include <stdint.h>

#define BSZ 8
#define N0 2048
#define N1 512
#define N2 128

// Split-fp16 head GEMMs (mma.sync; K doubled, A'=[hi|lo], B'=[hi|hi]):
//   gemm1: M=16384, N=1024, K'=2944; gemm2: N=512, K'=2048; gemm3: N=128(pad 50), K'=1024

// ---- scratch (device globals; allocations are forbidden) ----
__device__ int   g_perm1[N0];
__device__ int   g_perm2[N1];
__device__ int   g_ni0[BSZ*N0*32];
__device__ float g_dn0[BSZ*N0*32*3];
__device__ float g_fmA[BSZ*N0*96];
__device__ float g_ft [BSZ*N0*64];
__device__ float g_v1 [BSZ*N1*3];
__device__ int   g_ni1[BSZ*N1*32];
__device__ float g_dn1[BSZ*N1*32*3];
__device__ float g_fmB[BSZ*N1*192];
__device__ float g_v2 [BSZ*N2*3];
__device__ int   g_ni2[BSZ*N2*32];
__device__ float g_dn2[BSZ*N2*32*3];
__device__ float g_fmC[BSZ*N2*256];
__device__ float g_fglob[BSZ*256];
__device__ int   g_n1[BSZ*N0];
__device__ int   g_n2[BSZ*N0];

__device__ __half g_A1[(size_t)16384*2944];
__device__ __half g_W1[(size_t)1024 *2944];
__device__ __half g_A2[(size_t)16384*2048];
__device__ __half g_W2[(size_t)512  *2048];
__device__ __half g_A3[(size_t)16384*1024];
__device__ __half g_W3[(size_t)128  *1024];

__device__ __forceinline__ uint32_t smem_u32(const void* p){
  uint32_t a;
  asm("{ .reg .u64 t; cvta.to.shared.u64 t, %1; cvt.u32.u64 %0, t; }" : "=r"(a) : "l"(p));
  return a;
}
__device__ __forceinline__ void split_f16(float v, __half& hi, __half& lo){
  hi = __float2half_rn(v);
  lo = __float2half_rn(v - __half2float(hi));
}
__device__ __forceinline__ unsigned packh(__half a, __half b){
  return (unsigned)__half_as_ushort(a) | ((unsigned)__half_as_ushort(b) << 16);
}

// ---- threefry2x32 (exact JAX cipher) ----
__device__ __forceinline__ void tfry(unsigned k0, unsigned k1, unsigned &x0, unsigned &x1){
  unsigned ks2 = k0 ^ k1 ^ 0x1BD11BDAu;
  x0 += k0; x1 += k1;
#define TF_R(r) { x0 += x1; x1 = (x1<<(r))|(x1>>(32-(r))); x1 ^= x0; }
  TF_R(13) TF_R(15) TF_R(26) TF_R(6)   x0 += k1;  x1 += ks2 + 1u;
  TF_R(17) TF_R(29) TF_R(16) TF_R(24)  x0 += ks2; x1 += k0  + 2u;
  TF_R(13) TF_R(15) TF_R(26) TF_R(6)   x0 += k0;  x1 += k1  + 3u;
  TF_R(17) TF_R(29) TF_R(16) TF_R(24)  x0 += k1;  x1 += ks2 + 4u;
  TF_R(13) TF_R(15) TF_R(26) TF_R(6)   x0 += ks2; x1 += k0  + 5u;
#undef TF_R
}
__device__ __forceinline__ void tfry2(unsigned k0, unsigned k1, unsigned c0, unsigned c1,
                                      unsigned &o0, unsigned &o1){
  o0 = c0; o1 = c1; tfry(k0, k1, o0, o1);
}

__device__ void bitonic_sort(unsigned long long* sk, int* sv, int n, int tid, int nthr){
  for (int k=2;k<=n;k<<=1){
    for (int j=k>>1;j>0;j>>=1){
      for (int i=tid;i<n;i+=nthr){
        int ix=i^j;
        if (ix>i){
          bool up = ((i & k)==0);
          unsigned long long a=sk[i], c=sk[ix];
          if ((a>c)==up){
            sk[i]=c; sk[ix]=a;
            int t=sv[i]; sv[i]=sv[ix]; sv[ix]=t;
          }
        }
      }
      __syncthreads();
    }
  }
}

// jax.random.permutation, PARTITIONABLE threefry (modern JAX default)
__global__ void k_perm(){
  __shared__ unsigned long long sk[2048];
  __shared__ int sv[2048];
  int tid = threadIdx.x;   // 1024

  unsigned ck0, ck1; tfry2(0u, 42u, 0u, 1u, ck0, ck1);   // fold_in(key(42),1)
  for (int round=0; round<2; round++){
    unsigned nk0, nk1; tfry2(ck0, ck1, 0u, 0u, nk0, nk1);
    unsigned s0,  s1;  tfry2(ck0, ck1, 0u, 1u, s0,  s1);
    unsigned a0,a1; tfry2(s0, s1, 0u, (unsigned)tid,        a0, a1);
    unsigned b0,b1; tfry2(s0, s1, 0u, (unsigned)(tid+1024), b0, b1);
    unsigned bitsA = a0 ^ a1, bitsB = b0 ^ b1;
    if (round==0){ sv[tid]=tid; sv[tid+1024]=tid+1024; }
    __syncthreads();
    sk[tid]      = ((unsigned long long)bitsA<<32) | (unsigned)tid;
    sk[tid+1024] = ((unsigned long long)bitsB<<32) | (unsigned)(tid+1024);
    __syncthreads();
    bitonic_sort(sk, sv, 2048, tid, 1024);
    ck0=nk0; ck1=nk1;
  }
  g_perm1[tid]      = sv[tid];
  g_perm1[tid+1024] = sv[tid+1024];
  __syncthreads();

  unsigned f0, f1; tfry2(0u, 42u, 0u, 2u, f0, f1);        // fold_in(key(42),2)
  unsigned s0, s1; tfry2(f0, f1, 0u, 1u, s0, s1);
  if (tid < 512){
    unsigned a0,a1; tfry2(s0, s1, 0u, (unsigned)tid, a0, a1);
    sk[tid] = ((unsigned long long)(a0^a1)<<32) | (unsigned)tid;
    sv[tid] = tid;
  }
  __syncthreads();
  bitonic_sort(sk, sv, 512, tid, 1024);
  if (tid<512) g_perm2[tid]=sv[tid];
}

// ---- ball query ----
__global__ void k_ball(const float* __restrict__ verts, int Nv, float r2,
                       int* __restrict__ ni, float* __restrict__ dn){
  __shared__ int sidx[4][32];
  int b = blockIdx.y;
  int w = threadIdx.x>>5, lane = threadIdx.x&31;
  int v = blockIdx.x*4 + w;
  const float* vb = verts + (size_t)b*Nv*3;
  float cx = vb[v*3+0], cy = vb[v*3+1], cz = vb[v*3+2];
  int cnt = 0;
  for (int base=0; base<Nv && cnt<32; base+=32){
    int j = base + lane;
    float dx = __fsub_rn(cx, vb[j*3+0]);
    float dy = __fsub_rn(cy, vb[j*3+1]);
    float dz = __fsub_rn(cz, vb[j*3+2]);
    float sq = __fadd_rn(__fadd_rn(__fmul_rn(dx,dx),__fmul_rn(dy,dy)),__fmul_rn(dz,dz));
    unsigned m = __ballot_sync(0xffffffffu, !(sq > r2));
    while (m && cnt<32){
      int l = __ffs(m)-1; m &= m-1u;
      if (lane==0) sidx[w][cnt] = base + l;
      cnt++;
    }
  }
  __syncwarp();
  int first = sidx[w][0];
  int idx = (lane<cnt) ? sidx[w][lane] : first;
  ni[((size_t)(b*Nv)+v)*32 + lane] = idx;
  float nx = __fsub_rn(vb[idx*3+0], cx);
  float ny = __fsub_rn(vb[idx*3+1], cy);
  float nz = __fsub_rn(vb[idx*3+2], cz);
  float nrm = sqrtf(nx*nx + ny*ny + nz*nz);
  float den = fmaxf(nrm, 1e-12f);
  float* dp = dn + (((size_t)(b*Nv)+v)*32 + lane)*3;
  dp[0]=nx/den; dp[1]=ny/den; dp[2]=nz/den;
}

__global__ void k_surface(const float* __restrict__ dn, const float* __restrict__ d,
                          float* __restrict__ fmOut, int ldOut, int Nv){
  int b = blockIdx.y;
  int w = threadIdx.x>>5, lane = threadIdx.x&31;
  int v = blockIdx.x*8 + w;
  float u0=d[lane], u1=d[32+lane], u2=d[64+lane];
  float den = fmaxf(sqrtf(u0*u0+u1*u1+u2*u2), 1e-12f);
  u0/=den; u1/=den; u2/=den;
  const float* dp = dn + ((size_t)(b*Nv)+v)*96;
  float m = 0.f;
  #pragma unroll 4
  for (int n=0;n<32;n++){
    float t = dp[n*3+0]*u0 + dp[n*3+1]*u1 + dp[n*3+2]*u2;
    m = fmaxf(m, t);
  }
  fmOut[((size_t)(b*Nv)+v)*ldOut + lane] = m;
}

// ---- linear (R13 version): 4 vertices/block, 256 threads ----
__global__ void k_linear(const float* __restrict__ fm, int ld, int Cin,
                         const float* __restrict__ w, const float* __restrict__ bias,
                         float* __restrict__ ft, int Nv){
  __shared__ float sf[4][224];
  int b = blockIdx.y;
  int v0 = blockIdx.x*4;
  int tid = threadIdx.x;   // 256
  for (int idx=tid; idx<4*Cin; idx+=256){
    int vl = idx / Cin, c = idx % Cin;
    sf[vl][c] = fm[((size_t)(b*Nv) + v0+vl)*ld + c];
  }
  __syncthreads();
  int o = tid & 63, vl = tid >> 6;
  float acc = bias[o];
  for (int c=0;c<Cin;c++) acc += sf[vl][c] * w[c*64+o];
  ft[((size_t)(b*Nv) + v0+vl)*64 + o] = acc;
}

__global__ void k_act(const float* __restrict__ dn, const int* __restrict__ ni,
                      const float* __restrict__ dd, const float* __restrict__ ft,
                      float* __restrict__ fmOut, int ldOut, int Coff, int Nv){
  int b = blockIdx.y;
  int w = threadIdx.x>>5, lane = threadIdx.x&31;
  int v = blockIdx.x*8 + w;
  float u0=dd[lane], u1=dd[32+lane], u2=dd[64+lane];
  float den = fmaxf(sqrtf(u0*u0+u1*u1+u2*u2), 1e-12f);
  u0/=den; u1/=den; u2/=den;
  const float* dp  = dn + ((size_t)(b*Nv)+v)*96;
  const int*   nip = ni + ((size_t)(b*Nv)+v)*32;
  const float* ftb = ft + (size_t)b*Nv*64;
  float center = ftb[(size_t)v*64 + lane];
  float act = -FLT_MAX;
  for (int n=0;n<32;n++){
    int nb = nip[n];
    float t = fmaxf(dp[n*3+0]*u0 + dp[n*3+1]*u1 + dp[n*3+2]*u2, 0.f);
    float s = ftb[(size_t)nb*64 + 32 + lane];
    act = fmaxf(act, t*s);
  }
  fmOut[((size_t)(b*Nv)+v)*ldOut + Coff + lane] = fmaxf(center + act, 0.f);
}

__global__ void k_pool(const int* __restrict__ perm, const int* __restrict__ ni,
                       const float* __restrict__ fmIn, int ldIn, int C,
                       const float* __restrict__ vin, float* __restrict__ fmOut, int ldOut,
                       float* __restrict__ vout, int Nin, int Nout){
  int b = blockIdx.y, p = blockIdx.x;
  int v = perm[p];
  const int* nip = ni + ((size_t)(b*Nin)+v)*32;
  int j0=nip[0], j1=nip[1], j2=nip[2], j3=nip[3];
  const float* base = fmIn + (size_t)b*Nin*ldIn;
  for (int c=threadIdx.x; c<C; c+=blockDim.x){
    float m = fmaxf(fmaxf(base[(size_t)j0*ldIn+c], base[(size_t)j1*ldIn+c]),
                    fmaxf(base[(size_t)j2*ldIn+c], base[(size_t)j3*ldIn+c]));
    fmOut[((size_t)(b*Nout)+p)*ldOut + c] = m;
  }
  if (threadIdx.x<3)
    vout[((size_t)(b*Nout)+p)*3+threadIdx.x] = vin[((size_t)(b*Nin)+v)*3+threadIdx.x];
}

__global__ void k_global(const float* __restrict__ fmC, float* __restrict__ fg){
  int b = blockIdx.x, c = threadIdx.x;
  float m = -FLT_MAX;
  for (int v=0; v<N2; v++) m = fmaxf(m, fmC[((size_t)(b*N2)+v)*256 + c]);
  fg[b*256+c] = m;
}

__global__ void k_nearest(const float* __restrict__ q, const float* __restrict__ src,
                          int Nsrc, int* __restrict__ out){
  int b = blockIdx.y;
  int w = threadIdx.x>>5, lane = threadIdx.x&31;
  int v = blockIdx.x*4 + w;
  const float* qp = q + ((size_t)(b*N0)+v)*3;
  float qx=qp[0], qy=qp[1], qz=qp[2];
  float best = FLT_MAX; int bi = 0x7fffffff;
  for (int j=lane; j<Nsrc; j+=32){
    const float* s = src + ((size_t)(b*Nsrc)+j)*3;
    float dx=__fsub_rn(qx,s[0]), dy=__fsub_rn(qy,s[1]), dz=__fsub_rn(qz,s[2]);
    float sq=__fadd_rn(__fadd_rn(__fmul_rn(dx,dx),__fmul_rn(dy,dy)),__fmul_rn(dz,dz));
    if (sq < best){ best=sq; bi=j; }
  }
  for (int off=16; off; off>>=1){
    float ob = __shfl_down_sync(0xffffffffu, best, off);
    int   oi = __shfl_down_sync(0xffffffffu, bi,   off);
    if (ob < best || (ob==best && oi<bi)){ best=ob; bi=oi; }
  }
  if (lane==0) out[(size_t)b*N0+v] = bi;
}

// ---- fuse -> split-fp16 A1 [16384][2944] = [hi(1472)|lo]; packed 4B stores ----
__device__ __forceinline__ float fuse_fetch(int c, const float* fa, const float* fb,
                                            const float* fc, const float* fg,
                                            const float* onehot, int b){
  if (c>=1424) return 0.f;
  if      (c<32)   return fa[c];
  else if (c<96)   return fa[c-32];
  else if (c<192)  return fa[c-96];
  else if (c<320)  return fb[c-192];
  else if (c<480)  return fb[c-320];
  else if (c<672)  return fb[c-480];
  else if (c<896)  return fc[c-672];
  else if (c<1152) return fc[c-896];
  else if (c<1408) return fg[b*256 + (c-1152)];
  else             return onehot[b*16 + (c-1408)];
}

__global__ void k_fuse_split(const float* __restrict__ onehot, const float* __restrict__ fmA,
                             const float* __restrict__ fmB, const float* __restrict__ fmC,
                             const float* __restrict__ fg, const int* __restrict__ n1,
                             const int* __restrict__ n2, __half* __restrict__ A1){
  int b = blockIdx.y, v = blockIdx.x;
  int i1 = n1[b*N0+v], i2 = n2[b*N0+v];
  const float* fa = fmA + ((size_t)(b*N0)+v )*96;
  const float* fb = fmB + ((size_t)(b*N1)+i1)*192;
  const float* fc = fmC + ((size_t)(b*N2)+i2)*256;
  size_t row = (size_t)(b*N0 + v) * 2944;
  for (int c2=threadIdx.x; c2<736; c2+=256){
    int c = c2*2;
    float x0 = fuse_fetch(c,   fa, fb, fc, fg, onehot, b);
    float x1 = fuse_fetch(c+1, fa, fb, fc, fg, onehot, b);
    __half h0,l0,h1,l1;
    split_f16(x0,h0,l0); split_f16(x1,h1,l1);
    *(unsigned*)&A1[row + c]        = packh(h0,h1);
    *(unsigned*)&A1[row + 1472 + c] = packh(l0,l1);
  }
}

// ---- weight -> split-fp16 row-major [Npad][2*Kpad] = [hi | hi]; zero-pads ----
__global__ void k_wsplit(const float* __restrict__ w, int N, int K, int Kpad,
                         __half* __restrict__ out, int total){
  int idx = blockIdx.x*256 + threadIdx.x;
  if (idx >= total) return;
  int n = idx / Kpad, c = idx - n*Kpad;
  float v = (n < N && c < K) ? w[(size_t)n*K + c] : 0.f;
  __half hi = __float2half_rn(v);
  size_t base = (size_t)n * 2 * Kpad;
  out[base + c]        = hi;
  out[base + Kpad + c] = hi;
}

// ---- fp16 mma.sync GEMM (R13 baseline): BM=BN=128, BK=64, 2-stage, 2 CTAs/SM ----
#define MM_STG 2
__global__ void __launch_bounds__(256, 2)
k_mm(const __half* __restrict__ A, const __half* __restrict__ B,
     const float* __restrict__ bias, int K,
     __half* __restrict__ Anext, int Knext,
     float* __restrict__ Cfinal, int Nfinal)
{
  extern __shared__ char sm[];
  int tid = threadIdx.x, lane = tid&31, wid = tid>>5;
  int bn = blockIdx.x*128, bm = blockIdx.y*128;
  int wm = (wid>>2)*64, wn = (wid&3)*32;
  int nK = K >> 6;
  uint32_t sA0 = smem_u32(sm);
  uint32_t sB0 = sA0 + MM_STG*16384;

  float acc[4][4][4];
  #pragma unroll
  for (int i=0;i<4;i++)
    #pragma unroll
    for (int j=0;j<4;j++)
      #pragma unroll
      for (int q=0;q<4;q++) acc[i][j][q]=0.f;

  #define MM_ISSUE(KT) do{ \
    int _s = (KT) % MM_STG; \
    _Pragma("unroll") \
    for (int it=0; it<4; it++){ \
      int idx = it*256 + tid; \
      int r = idx>>3, c = idx&7; \
      uint32_t sw = ((uint32_t)(c ^ (r&7)))<<4; \
      uint32_t sa = sA0 + _s*16384 + r*128 + sw; \
      const void* ga = A + (size_t)(bm+r)*K + (KT)*64 + c*8; \
      asm volatile("cp.async.cg.shared.global [%0], [%1], 16;" :: "r"(sa), "l"(ga)); \
      uint32_t sb = sB0 + _s*16384 + r*128 + sw; \
      const void* gb = B + (size_t)(bn+r)*K + (KT)*64 + c*8; \
      asm volatile("cp.async.cg.shared.global [%0], [%1], 16;" :: "r"(sb), "l"(gb)); \
    } \
    asm volatile("cp.async.commit_group;" ::: "memory"); \
  } while(0)

  MM_ISSUE(0);

  for (int kt=0; kt<nK; kt++){
    int s = kt % MM_STG;
    asm volatile("cp.async.wait_group 0;" ::: "memory");
    __syncthreads();
    if (kt+1 < nK) MM_ISSUE(kt+1);
    uint32_t ab = sA0 + s*16384;
    uint32_t bb = sB0 + s*16384;
    #pragma unroll
    for (int kk=0; kk<4; kk++){
      uint32_t af[4][4], bfr[2][4];
      #pragma unroll
      for (int fm=0; fm<4; fm++){
        int row = wm + fm*16 + (lane&15);
        int ch  = kk*2 + (lane>>4);
        uint32_t ad = ab + row*128 + ((uint32_t)(ch ^ (row&7))<<4);
        asm volatile("ldmatrix.sync.aligned.m8n8.x4.shared.b16 {%0,%1,%2,%3}, [%4];"
          : "=r"(af[fm][0]),"=r"(af[fm][1]),"=r"(af[fm][2]),"=r"(af[fm][3]) : "r"(ad));
      }
      #pragma unroll
      for (int fp=0; fp<2; fp++){
        int row = wn + fp*16 + ((lane>>4)&1)*8 + (lane&7);
        int ch  = kk*2 + ((lane>>3)&1);
        uint32_t bd = bb + row*128 + ((uint32_t)(ch ^ (row&7))<<4);
        asm volatile("ldmatrix.sync.aligned.m8n8.x4.shared.b16 {%0,%1,%2,%3}, [%4];"
          : "=r"(bfr[fp][0]),"=r"(bfr[fp][1]),"=r"(bfr[fp][2]),"=r"(bfr[fp][3]) : "r"(bd));
      }
      #pragma unroll
      for (int fm=0; fm<4; fm++)
        #pragma unroll
        for (int fn=0; fn<4; fn++){
          uint32_t b0 = bfr[fn>>1][(fn&1)*2], b1 = bfr[fn>>1][(fn&1)*2+1];
          asm volatile("mma.sync.aligned.m16n8k16.row.col.f32.f16.f16.f32 "
            "{%0,%1,%2,%3}, {%4,%5,%6,%7}, {%8,%9}, {%0,%1,%2,%3};"
            : "+f"(acc[fm][fn][0]), "+f"(acc[fm][fn][1]), "+f"(acc[fm][fn][2]), "+f"(acc[fm][fn][3])
            : "r"(af[fm][0]), "r"(af[fm][1]), "r"(af[fm][2]), "r"(af[fm][3]), "r"(b0), "r"(b1));
        }
    }
    __syncthreads();
  }

  if (Anext){
    #pragma unroll
    for (int fm=0; fm<4; fm++){
      #pragma unroll
      for (int fn=0; fn<4; fn++){
        int r0 = wm + fm*16 + (lane>>2);
        int c0 = wn + fn*8 + (lane&3)*2;
        float b0 = bias[bn + c0], b1 = bias[bn + c0 + 1];
        #pragma unroll
        for (int h=0; h<2; h++){
          int r = r0 + h*8;
          float v0 = fmaxf(acc[fm][fn][h*2+0] + b0, 0.f);
          float v1 = fmaxf(acc[fm][fn][h*2+1] + b1, 0.f);
          __half h0,l0,h1,l1;
          split_f16(v0,h0,l0); split_f16(v1,h1,l1);
          *(unsigned*)(sm + r*256 + c0*2)         = packh(h0,h1);
          *(unsigned*)(sm + 32768 + r*256 + c0*2) = packh(l0,l1);
        }
      }
    }
    __syncthreads();
    size_t rstride = 2*(size_t)Knext;
    #pragma unroll
    for (int seg=0; seg<2; seg++){
      int srcoff = seg*32768;
      size_t segoff = (size_t)seg*Knext;
      #pragma unroll
      for (int p=0; p<8; p++){
        int idx = p*256 + tid;
        int r = idx>>4, cb = (idx&15)*16;
        uint4 val = *(const uint4*)(sm + srcoff + r*256 + cb);
        *(uint4*)((char*)(Anext + (size_t)(bm+r)*rstride + segoff + bn) + cb) = val;
      }
    }
  } else {
    #pragma unroll
    for (int fm=0; fm<4; fm++){
      #pragma unroll
      for (int fn=0; fn<4; fn++){
        int r0 = wm + fm*16 + (lane>>2);
        int c0 = wn + fn*8 + (lane&3)*2;
        #pragma unroll
        for (int h=0; h<2; h++){
          int m = bm + r0 + h*8;
          int n0g = bn + c0;
          if (n0g   < Nfinal) Cfinal[(size_t)m*Nfinal + n0g  ] = acc[fm][fn][h*2+0] + bias[n0g];
          if (n0g+1 < Nfinal) Cfinal[(size_t)m*Nfinal + n0g+1] = acc[fm][fn][h*2+1] + bias[n0g+1];
        }
      }
    }
  }
  #undef MM_ISSUE
}

// ---- host launch ----
static void* sym_addr_(const void* s){ void* p=nullptr; cudaGetSymbolAddress(&p, s); return p; }

extern "C" void kernel_launch(void* const* d_in, const int* in_sizes, int n_in,
                              void* d_out, int out_size){
  const float* vertices = (const float*)d_in[0];
  const float* onehot   = (const float*)d_in[1];
  const float* d0       = (const float*)d_in[2];
  const float* W[8]; const float* Bb[8]; const float* DD[8];
  for (int i=1;i<=7;i++){
    W[i]  = (const float*)d_in[3*i];
    Bb[i] = (const float*)d_in[3*i+1];
    DD[i] = (const float*)d_in[3*i+2];
  }
  const float* cw1=(const float*)d_in[24]; const float* cb1=(const float*)d_in[25];
  const float* cw2=(const float*)d_in[26]; const float* cb2=(const float*)d_in[27];
  const float* cw3=(const float*)d_in[28]; const float* cb3=(const float*)d_in[29];
  float* out = (float*)d_out;

  int*   perm1=(int*)  sym_addr_(g_perm1); int*   perm2=(int*)  sym_addr_(g_perm2);
  int*   ni0  =(int*)  sym_addr_(g_ni0);   float* dn0  =(float*)sym_addr_(g_dn0);
  float* fmA  =(float*)sym_addr_(g_fmA);   float* ft   =(float*)sym_addr_(g_ft);
  float* v1   =(float*)sym_addr_(g_v1);
  int*   ni1  =(int*)  sym_addr_(g_ni1);   float* dn1  =(float*)sym_addr_(g_dn1);
  float* fmB  =(float*)sym_addr_(g_fmB);   float* v2   =(float*)sym_addr_(g_v2);
  int*   ni2  =(int*)  sym_addr_(g_ni2);   float* dn2  =(float*)sym_addr_(g_dn2);
  float* fmC  =(float*)sym_addr_(g_fmC);   float* fg   =(float*)sym_addr_(g_fglob);
  int*   n1   =(int*)  sym_addr_(g_n1);    int*   n2   =(int*)  sym_addr_(g_n2);
  __half* A1=(__half*)sym_addr_(g_A1);  __half* W1=(__half*)sym_addr_(g_W1);
  __half* A2=(__half*)sym_addr_(g_A2);  __half* W2=(__half*)sym_addr_(g_W2);
  __half* A3=(__half*)sym_addr_(g_A3);  __half* W3=(__half*)sym_addr_(g_W3);

  const float R2A = (float)(0.25*0.25);
  const float R2B = (float)(0.39*0.39);
  const float R2C = (float)(0.63*0.63);

  const int DSMEM = MM_STG*16384*2;   // 64KB
  cudaFuncSetAttribute(k_mm, cudaFuncAttributeMaxDynamicSharedMemorySize, DSMEM);

  k_perm<<<1,1024>>>();

  // Stage A (2048 pts)
  k_ball   <<<dim3(N0/4,BSZ),128>>>(vertices, N0, R2A, ni0, dn0);
  k_surface<<<dim3(N0/8,BSZ),256>>>(dn0, d0, fmA, 96, N0);
  k_linear <<<dim3(N0/4,BSZ),256>>>(fmA, 96, 32,  W[1], Bb[1], ft, N0);
  k_act    <<<dim3(N0/8,BSZ),256>>>(dn0, ni0, DD[1], ft, fmA, 96, 32, N0);
  k_linear <<<dim3(N0/4,BSZ),256>>>(fmA, 96, 64,  W[2], Bb[2], ft, N0);
  k_act    <<<dim3(N0/8,BSZ),256>>>(dn0, ni0, DD[2], ft, fmA, 96, 64, N0);
  k_pool   <<<dim3(N1,BSZ),128>>>(perm1, ni0, fmA, 96, 96, vertices, fmB, 192, v1, N0, N1);

  // Stage B (512 pts)
  k_ball   <<<dim3(N1/4,BSZ),128>>>(v1, N1, R2B, ni1, dn1);
  k_linear <<<dim3(N1/4,BSZ),256>>>(fmB, 192, 96,  W[3], Bb[3], ft, N1);
  k_act    <<<dim3(N1/8,BSZ),256>>>(dn1, ni1, DD[3], ft, fmB, 192, 96, N1);
  k_linear <<<dim3(N1/4,BSZ),256>>>(fmB, 192, 128, W[4], Bb[4], ft, N1);
  k_act    <<<dim3(N1/8,BSZ),256>>>(dn1, ni1, DD[4], ft, fmB, 192, 128, N1);
  k_linear <<<dim3(N1/4,BSZ),256>>>(fmB, 192, 160, W[5], Bb[5], ft, N1);
  k_act    <<<dim3(N1/8,BSZ),256>>>(dn1, ni1, DD[5], ft, fmB, 192, 160, N1);
  k_pool   <<<dim3(N2,BSZ),128>>>(perm2, ni1, fmB, 192, 192, v1, fmC, 256, v2, N1, N2);

  // Stage C (128 pts)
  k_ball   <<<dim3(N2/4,BSZ),128>>>(v2, N2, R2C, ni2, dn2);
  k_linear <<<dim3(N2/4,BSZ),256>>>(fmC, 256, 192, W[6], Bb[6], ft, N2);
  k_act    <<<dim3(N2/8,BSZ),256>>>(dn2, ni2, DD[6], ft, fmC, 256, 192, N2);
  k_linear <<<dim3(N2/4,BSZ),256>>>(fmC, 256, 224, W[7], Bb[7], ft, N2);
  k_act    <<<dim3(N2/8,BSZ),256>>>(dn2, ni2, DD[7], ft, fmC, 256, 224, N2);
  k_global <<<BSZ,256>>>(fmC, fg);

  // Fuse + head (split-fp16 mma.sync)
  k_nearest<<<dim3(N0/4,BSZ),128>>>(vertices, v1, N1, n1);
  k_nearest<<<dim3(N0/4,BSZ),128>>>(vertices, v2, N2, n2);
  k_wsplit <<<(1024*1472+255)/256,256>>>(cw1, 1024, 1424, 1472, W1, 1024*1472);
  k_wsplit <<<( 512*1024+255)/256,256>>>(cw2,  512, 1024, 1024, W2,  512*1024);
  k_wsplit <<<( 128* 512+255)/256,256>>>(cw3,   50,  512,  512, W3,  128* 512);
  k_fuse_split<<<dim3(N0,BSZ),256>>>(onehot, fmA, fmB, fmC, fg, n1, n2, A1);
  k_mm<<<dim3(8,128),256,DSMEM>>>(A1, W1, cb1, 2944, A2, 1024, nullptr, 0);
  k_mm<<<dim3(4,128),256,DSMEM>>>(A2, W2, cb2, 2048, A3,  512, nullptr, 0);
  k_mm<<<dim3(1,128),256,DSMEM>>>(A3, W3, cb3, 1024, nullptr, 0, out, 50);
}

// round 16
// speedup vs baseline: 1.0932x; 1.0149x over previous
#include <cuda_runtime.h>
#include <cuda_bf16.h>
#include <cuda_fp16.h>
#include <math.h>
#include <float.h>
#include <stdint.h>

#define BSZ 8
#define N0 2048
#define N1 512
#define N2 128

// Split-fp16 head GEMMs (mma.sync; K doubled, A'=[hi|lo], B'=[hi|hi]):
//   gemm1: M=16384, N=1024, K'=2944; gemm2: N=512, K'=2048; gemm3: N=128(pad 50), K'=1024

// ---- scratch (device globals; allocations are forbidden) ----
__device__ int   g_perm1[N0];
__device__ int   g_perm2[N1];
__device__ int   g_ni0[BSZ*N0*32];
__device__ float g_dn0[BSZ*N0*32*3];
__device__ float g_fmA[BSZ*N0*96];
__device__ float g_ft [BSZ*N0*64];
__device__ float g_v1 [BSZ*N1*3];
__device__ int   g_ni1[BSZ*N1*32];
__device__ float g_dn1[BSZ*N1*32*3];
__device__ float g_fmB[BSZ*N1*192];
__device__ float g_v2 [BSZ*N2*3];
__device__ int   g_ni2[BSZ*N2*32];
__device__ float g_dn2[BSZ*N2*32*3];
__device__ float g_fmC[BSZ*N2*256];
__device__ float g_fglob[BSZ*256];
__device__ int   g_n1[BSZ*N0];
__device__ int   g_n2[BSZ*N0];

__device__ __half g_A1[(size_t)16384*2944];
__device__ __half g_W1[(size_t)1024 *2944];
__device__ __half g_A2[(size_t)16384*2048];
__device__ __half g_W2[(size_t)512  *2048];
__device__ __half g_A3[(size_t)16384*1024];
__device__ __half g_W3[(size_t)128  *1024];

__device__ __forceinline__ uint32_t smem_u32(const void* p){
  uint32_t a;
  asm("{ .reg .u64 t; cvta.to.shared.u64 t, %1; cvt.u32.u64 %0, t; }" : "=r"(a) : "l"(p));
  return a;
}
__device__ __forceinline__ void split_f16(float v, __half& hi, __half& lo){
  hi = __float2half_rn(v);
  lo = __float2half_rn(v - __half2float(hi));
}
__device__ __forceinline__ unsigned packh(__half a, __half b){
  return (unsigned)__half_as_ushort(a) | ((unsigned)__half_as_ushort(b) << 16);
}

// ---- threefry2x32 (exact JAX cipher) ----
__device__ __forceinline__ void tfry(unsigned k0, unsigned k1, unsigned &x0, unsigned &x1){
  unsigned ks2 = k0 ^ k1 ^ 0x1BD11BDAu;
  x0 += k0; x1 += k1;
#define TF_R(r) { x0 += x1; x1 = (x1<<(r))|(x1>>(32-(r))); x1 ^= x0; }
  TF_R(13) TF_R(15) TF_R(26) TF_R(6)   x0 += k1;  x1 += ks2 + 1u;
  TF_R(17) TF_R(29) TF_R(16) TF_R(24)  x0 += ks2; x1 += k0  + 2u;
  TF_R(13) TF_R(15) TF_R(26) TF_R(6)   x0 += k0;  x1 += k1  + 3u;
  TF_R(17) TF_R(29) TF_R(16) TF_R(24)  x0 += k1;  x1 += ks2 + 4u;
  TF_R(13) TF_R(15) TF_R(26) TF_R(6)   x0 += ks2; x1 += k0  + 5u;
#undef TF_R
}
__device__ __forceinline__ void tfry2(unsigned k0, unsigned k1, unsigned c0, unsigned c1,
                                      unsigned &o0, unsigned &o1){
  o0 = c0; o1 = c1; tfry(k0, k1, o0, o1);
}

__device__ void bitonic_sort(unsigned long long* sk, int* sv, int n, int tid, int nthr){
  for (int k=2;k<=n;k<<=1){
    for (int j=k>>1;j>0;j>>=1){
      for (int i=tid;i<n;i+=nthr){
        int ix=i^j;
        if (ix>i){
          bool up = ((i & k)==0);
          unsigned long long a=sk[i], c=sk[ix];
          if ((a>c)==up){
            sk[i]=c; sk[ix]=a;
            int t=sv[i]; sv[i]=sv[ix]; sv[ix]=t;
          }
        }
      }
      __syncthreads();
    }
  }
}

// jax.random.permutation, PARTITIONABLE threefry (modern JAX default)
__global__ void k_perm(){
  __shared__ unsigned long long sk[2048];
  __shared__ int sv[2048];
  int tid = threadIdx.x;   // 1024

  unsigned ck0, ck1; tfry2(0u, 42u, 0u, 1u, ck0, ck1);   // fold_in(key(42),1)
  for (int round=0; round<2; round++){
    unsigned nk0, nk1; tfry2(ck0, ck1, 0u, 0u, nk0, nk1);
    unsigned s0,  s1;  tfry2(ck0, ck1, 0u, 1u, s0,  s1);
    unsigned a0,a1; tfry2(s0, s1, 0u, (unsigned)tid,        a0, a1);
    unsigned b0,b1; tfry2(s0, s1, 0u, (unsigned)(tid+1024), b0, b1);
    unsigned bitsA = a0 ^ a1, bitsB = b0 ^ b1;
    if (round==0){ sv[tid]=tid; sv[tid+1024]=tid+1024; }
    __syncthreads();
    sk[tid]      = ((unsigned long long)bitsA<<32) | (unsigned)tid;
    sk[tid+1024] = ((unsigned long long)bitsB<<32) | (unsigned)(tid+1024);
    __syncthreads();
    bitonic_sort(sk, sv, 2048, tid, 1024);
    ck0=nk0; ck1=nk1;
  }
  g_perm1[tid]      = sv[tid];
  g_perm1[tid+1024] = sv[tid+1024];
  __syncthreads();

  unsigned f0, f1; tfry2(0u, 42u, 0u, 2u, f0, f1);        // fold_in(key(42),2)
  unsigned s0, s1; tfry2(f0, f1, 0u, 1u, s0, s1);
  if (tid < 512){
    unsigned a0,a1; tfry2(s0, s1, 0u, (unsigned)tid, a0, a1);
    sk[tid] = ((unsigned long long)(a0^a1)<<32) | (unsigned)tid;
    sv[tid] = tid;
  }
  __syncthreads();
  bitonic_sort(sk, sv, 512, tid, 1024);
  if (tid<512) g_perm2[tid]=sv[tid];
}

// ---- ball query; optionally fused conv_surface (stage A: fm0 != nullptr) ----
__global__ void k_ball(const float* __restrict__ verts, int Nv, float r2,
                       int* __restrict__ ni, float* __restrict__ dn,
                       const float* __restrict__ d0, float* __restrict__ fm0, int ldOut){
  __shared__ int sidx[4][32];
  __shared__ float sdn[4][32][3];
  int b = blockIdx.y;
  int w = threadIdx.x>>5, lane = threadIdx.x&31;
  int v = blockIdx.x*4 + w;
  const float* vb = verts + (size_t)b*Nv*3;
  float cx = vb[v*3+0], cy = vb[v*3+1], cz = vb[v*3+2];
  int cnt = 0;
  for (int base=0; base<Nv && cnt<32; base+=32){
    int j = base + lane;
    float dx = __fsub_rn(cx, vb[j*3+0]);
    float dy = __fsub_rn(cy, vb[j*3+1]);
    float dz = __fsub_rn(cz, vb[j*3+2]);
    float sq = __fadd_rn(__fadd_rn(__fmul_rn(dx,dx),__fmul_rn(dy,dy)),__fmul_rn(dz,dz));
    unsigned m = __ballot_sync(0xffffffffu, !(sq > r2));
    while (m && cnt<32){
      int l = __ffs(m)-1; m &= m-1u;
      if (lane==0) sidx[w][cnt] = base + l;
      cnt++;
    }
  }
  __syncwarp();
  int first = sidx[w][0];
  int idx = (lane<cnt) ? sidx[w][lane] : first;
  ni[((size_t)(b*Nv)+v)*32 + lane] = idx;
  float nx = __fsub_rn(vb[idx*3+0], cx);
  float ny = __fsub_rn(vb[idx*3+1], cy);
  float nz = __fsub_rn(vb[idx*3+2], cz);
  float nrm = sqrtf(nx*nx + ny*ny + nz*nz);
  float den = fmaxf(nrm, 1e-12f);
  float d0v = nx/den, d1v = ny/den, d2v = nz/den;
  float* dp = dn + (((size_t)(b*Nv)+v)*32 + lane)*3;
  dp[0]=d0v; dp[1]=d1v; dp[2]=d2v;

  if (fm0){
    sdn[w][lane][0]=d0v; sdn[w][lane][1]=d1v; sdn[w][lane][2]=d2v;
    __syncwarp();
    float u0=d0[lane], u1=d0[32+lane], u2=d0[64+lane];
    float dnm = fmaxf(sqrtf(u0*u0+u1*u1+u2*u2), 1e-12f);
    u0/=dnm; u1/=dnm; u2/=dnm;
    float m = 0.f;
    #pragma unroll 4
    for (int n=0;n<32;n++){
      float t = sdn[w][n][0]*u0 + sdn[w][n][1]*u1 + sdn[w][n][2]*u2;
      m = fmaxf(m, t);
    }
    fm0[((size_t)(b*Nv)+v)*ldOut + lane] = m;
  }
}

// ---- linear (R13 version): 4 vertices/block, 256 threads ----
__global__ void k_linear(const float* __restrict__ fm, int ld, int Cin,
                         const float* __restrict__ w, const float* __restrict__ bias,
                         float* __restrict__ ft, int Nv){
  __shared__ float sf[4][224];
  int b = blockIdx.y;
  int v0 = blockIdx.x*4;
  int tid = threadIdx.x;   // 256
  for (int idx=tid; idx<4*Cin; idx+=256){
    int vl = idx / Cin, c = idx % Cin;
    sf[vl][c] = fm[((size_t)(b*Nv) + v0+vl)*ld + c];
  }
  __syncthreads();
  int o = tid & 63, vl = tid >> 6;
  float acc = bias[o];
  for (int c=0;c<Cin;c++) acc += sf[vl][c] * w[c*64+o];
  ft[((size_t)(b*Nv) + v0+vl)*64 + o] = acc;
}

__global__ void k_act(const float* __restrict__ dn, const int* __restrict__ ni,
                      const float* __restrict__ dd, const float* __restrict__ ft,
                      float* __restrict__ fmOut, int ldOut, int Coff, int Nv){
  int b = blockIdx.y;
  int w = threadIdx.x>>5, lane = threadIdx.x&31;
  int v = blockIdx.x*8 + w;
  float u0=dd[lane], u1=dd[32+lane], u2=dd[64+lane];
  float den = fmaxf(sqrtf(u0*u0+u1*u1+u2*u2), 1e-12f);
  u0/=den; u1/=den; u2/=den;
  const float* dp  = dn + ((size_t)(b*Nv)+v)*96;
  const int*   nip = ni + ((size_t)(b*Nv)+v)*32;
  const float* ftb = ft + (size_t)b*Nv*64;
  float center = ftb[(size_t)v*64 + lane];
  float act = -FLT_MAX;
  for (int n=0;n<32;n++){
    int nb = nip[n];
    float t = fmaxf(dp[n*3+0]*u0 + dp[n*3+1]*u1 + dp[n*3+2]*u2, 0.f);
    float s = ftb[(size_t)nb*64 + 32 + lane];
    act = fmaxf(act, t*s);
  }
  fmOut[((size_t)(b*Nv)+v)*ldOut + Coff + lane] = fmaxf(center + act, 0.f);
}

__global__ void k_pool(const int* __restrict__ perm, const int* __restrict__ ni,
                       const float* __restrict__ fmIn, int ldIn, int C,
                       const float* __restrict__ vin, float* __restrict__ fmOut, int ldOut,
                       float* __restrict__ vout, int Nin, int Nout){
  int b = blockIdx.y, p = blockIdx.x;
  int v = perm[p];
  const int* nip = ni + ((size_t)(b*Nin)+v)*32;
  int j0=nip[0], j1=nip[1], j2=nip[2], j3=nip[3];
  const float* base = fmIn + (size_t)b*Nin*ldIn;
  for (int c=threadIdx.x; c<C; c+=blockDim.x){
    float m = fmaxf(fmaxf(base[(size_t)j0*ldIn+c], base[(size_t)j1*ldIn+c]),
                    fmaxf(base[(size_t)j2*ldIn+c], base[(size_t)j3*ldIn+c]));
    fmOut[((size_t)(b*Nout)+p)*ldOut + c] = m;
  }
  if (threadIdx.x<3)
    vout[((size_t)(b*Nout)+p)*3+threadIdx.x] = vin[((size_t)(b*Nin)+v)*3+threadIdx.x];
}

__global__ void k_global(const float* __restrict__ fmC, float* __restrict__ fg){
  int b = blockIdx.x, c = threadIdx.x;
  float m = -FLT_MAX;
  for (int v=0; v<N2; v++) m = fmaxf(m, fmC[((size_t)(b*N2)+v)*256 + c]);
  fg[b*256+c] = m;
}

// ---- nearest (both targets in one launch; z=0 -> v1/n1, z=1 -> v2/n2) ----
__global__ void k_nearest2(const float* __restrict__ q, const float* __restrict__ src1,
                           const float* __restrict__ src2, int* __restrict__ out1,
                           int* __restrict__ out2){
  int b = blockIdx.y;
  int w = threadIdx.x>>5, lane = threadIdx.x&31;
  int v = blockIdx.x*4 + w;
  const float* src = blockIdx.z ? src2 : src1;
  int Nsrc = blockIdx.z ? N2 : N1;
  int* out = blockIdx.z ? out2 : out1;
  const float* qp = q + ((size_t)(b*N0)+v)*3;
  float qx=qp[0], qy=qp[1], qz=qp[2];
  float best = FLT_MAX; int bi = 0x7fffffff;
  for (int j=lane; j<Nsrc; j+=32){
    const float* s = src + ((size_t)(b*Nsrc)+j)*3;
    float dx=__fsub_rn(qx,s[0]), dy=__fsub_rn(qy,s[1]), dz=__fsub_rn(qz,s[2]);
    float sq=__fadd_rn(__fadd_rn(__fmul_rn(dx,dx),__fmul_rn(dy,dy)),__fmul_rn(dz,dz));
    if (sq < best){ best=sq; bi=j; }
  }
  for (int off=16; off; off>>=1){
    float ob = __shfl_down_sync(0xffffffffu, best, off);
    int   oi = __shfl_down_sync(0xffffffffu, bi,   off);
    if (ob < best || (ob==best && oi<bi)){ best=ob; bi=oi; }
  }
  if (lane==0) out[(size_t)b*N0+v] = bi;
}

// ---- fuse -> split-fp16 A1 [16384][2944] = [hi(1472)|lo]; packed 4B stores ----
__device__ __forceinline__ float fuse_fetch(int c, const float* fa, const float* fb,
                                            const float* fc, const float* fg,
                                            const float* onehot, int b){
  if (c>=1424) return 0.f;
  if      (c<32)   return fa[c];
  else if (c<96)   return fa[c-32];
  else if (c<192)  return fa[c-96];
  else if (c<320)  return fb[c-192];
  else if (c<480)  return fb[c-320];
  else if (c<672)  return fb[c-480];
  else if (c<896)  return fc[c-672];
  else if (c<1152) return fc[c-896];
  else if (c<1408) return fg[b*256 + (c-1152)];
  else             return onehot[b*16 + (c-1408)];
}

__global__ void k_fuse_split(const float* __restrict__ onehot, const float* __restrict__ fmA,
                             const float* __restrict__ fmB, const float* __restrict__ fmC,
                             const float* __restrict__ fg, const int* __restrict__ n1,
                             const int* __restrict__ n2, __half* __restrict__ A1){
  int b = blockIdx.y, v = blockIdx.x;
  int i1 = n1[b*N0+v], i2 = n2[b*N0+v];
  const float* fa = fmA + ((size_t)(b*N0)+v )*96;
  const float* fb = fmB + ((size_t)(b*N1)+i1)*192;
  const float* fc = fmC + ((size_t)(b*N2)+i2)*256;
  size_t row = (size_t)(b*N0 + v) * 2944;
  for (int c2=threadIdx.x; c2<736; c2+=256){
    int c = c2*2;
    float x0 = fuse_fetch(c,   fa, fb, fc, fg, onehot, b);
    float x1 = fuse_fetch(c+1, fa, fb, fc, fg, onehot, b);
    __half h0,l0,h1,l1;
    split_f16(x0,h0,l0); split_f16(x1,h1,l1);
    *(unsigned*)&A1[row + c]        = packh(h0,h1);
    *(unsigned*)&A1[row + 1472 + c] = packh(l0,l1);
  }
}

// ---- all three weight splits in one launch: [hi | hi] per row; zero-pads ----
#define WT1 (1024*1472)
#define WT2 (512*1024)
#define WT3 (128*512)
__global__ void k_wsplit_all(const float* __restrict__ w1, const float* __restrict__ w2,
                             const float* __restrict__ w3, __half* __restrict__ o1,
                             __half* __restrict__ o2, __half* __restrict__ o3){
  int idx = blockIdx.x*256 + threadIdx.x;
  const float* w; __half* out; int N, K, Kpad;
  if (idx < WT1){ w=w1; out=o1; N=1024; K=1424; Kpad=1472; }
  else if (idx < WT1+WT2){ idx-=WT1; w=w2; out=o2; N=512; K=1024; Kpad=1024; }
  else if (idx < WT1+WT2+WT3){ idx-=WT1+WT2; w=w3; out=o3; N=50; K=512; Kpad=512; }
  else return;
  int n = idx / Kpad, c = idx - n*Kpad;
  float v = (n < N && c < K) ? w[(size_t)n*K + c] : 0.f;
  __half hi = __float2half_rn(v);
  size_t base = (size_t)n * 2 * Kpad;
  out[base + c]        = hi;
  out[base + Kpad + c] = hi;
}

// ---- fp16 mma.sync GEMM (R13 baseline): BM=BN=128, BK=64, 2-stage, 2 CTAs/SM ----
#define MM_STG 2
__global__ void __launch_bounds__(256, 2)
k_mm(const __half* __restrict__ A, const __half* __restrict__ B,
     const float* __restrict__ bias, int K,
     __half* __restrict__ Anext, int Knext,
     float* __restrict__ Cfinal, int Nfinal)
{
  extern __shared__ char sm[];
  int tid = threadIdx.x, lane = tid&31, wid = tid>>5;
  int bn = blockIdx.x*128, bm = blockIdx.y*128;
  int wm = (wid>>2)*64, wn = (wid&3)*32;
  int nK = K >> 6;
  uint32_t sA0 = smem_u32(sm);
  uint32_t sB0 = sA0 + MM_STG*16384;

  float acc[4][4][4];
  #pragma unroll
  for (int i=0;i<4;i++)
    #pragma unroll
    for (int j=0;j<4;j++)
      #pragma unroll
      for (int q=0;q<4;q++) acc[i][j][q]=0.f;

  #define MM_ISSUE(KT) do{ \
    int _s = (KT) % MM_STG; \
    _Pragma("unroll") \
    for (int it=0; it<4; it++){ \
      int idx = it*256 + tid; \
      int r = idx>>3, c = idx&7; \
      uint32_t sw = ((uint32_t)(c ^ (r&7)))<<4; \
      uint32_t sa = sA0 + _s*16384 + r*128 + sw; \
      const void* ga = A + (size_t)(bm+r)*K + (KT)*64 + c*8; \
      asm volatile("cp.async.cg.shared.global [%0], [%1], 16;" :: "r"(sa), "l"(ga)); \
      uint32_t sb = sB0 + _s*16384 + r*128 + sw; \
      const void* gb = B + (size_t)(bn+r)*K + (KT)*64 + c*8; \
      asm volatile("cp.async.cg.shared.global [%0], [%1], 16;" :: "r"(sb), "l"(gb)); \
    } \
    asm volatile("cp.async.commit_group;" ::: "memory"); \
  } while(0)

  MM_ISSUE(0);

  for (int kt=0; kt<nK; kt++){
    int s = kt % MM_STG;
    asm volatile("cp.async.wait_group 0;" ::: "memory");
    __syncthreads();
    if (kt+1 < nK) MM_ISSUE(kt+1);
    uint32_t ab = sA0 + s*16384;
    uint32_t bb = sB0 + s*16384;
    #pragma unroll
    for (int kk=0; kk<4; kk++){
      uint32_t af[4][4], bfr[2][4];
      #pragma unroll
      for (int fm=0; fm<4; fm++){
        int row = wm + fm*16 + (lane&15);
        int ch  = kk*2 + (lane>>4);
        uint32_t ad = ab + row*128 + ((uint32_t)(ch ^ (row&7))<<4);
        asm volatile("ldmatrix.sync.aligned.m8n8.x4.shared.b16 {%0,%1,%2,%3}, [%4];"
          : "=r"(af[fm][0]),"=r"(af[fm][1]),"=r"(af[fm][2]),"=r"(af[fm][3]) : "r"(ad));
      }
      #pragma unroll
      for (int fp=0; fp<2; fp++){
        int row = wn + fp*16 + ((lane>>4)&1)*8 + (lane&7);
        int ch  = kk*2 + ((lane>>3)&1);
        uint32_t bd = bb + row*128 + ((uint32_t)(ch ^ (row&7))<<4);
        asm volatile("ldmatrix.sync.aligned.m8n8.x4.shared.b16 {%0,%1,%2,%3}, [%4];"
          : "=r"(bfr[fp][0]),"=r"(bfr[fp][1]),"=r"(bfr[fp][2]),"=r"(bfr[fp][3]) : "r"(bd));
      }
      #pragma unroll
      for (int fm=0; fm<4; fm++)
        #pragma unroll
        for (int fn=0; fn<4; fn++){
          uint32_t b0 = bfr[fn>>1][(fn&1)*2], b1 = bfr[fn>>1][(fn&1)*2+1];
          asm volatile("mma.sync.aligned.m16n8k16.row.col.f32.f16.f16.f32 "
            "{%0,%1,%2,%3}, {%4,%5,%6,%7}, {%8,%9}, {%0,%1,%2,%3};"
            : "+f"(acc[fm][fn][0]), "+f"(acc[fm][fn][1]), "+f"(acc[fm][fn][2]), "+f"(acc[fm][fn][3])
            : "r"(af[fm][0]), "r"(af[fm][1]), "r"(af[fm][2]), "r"(af[fm][3]), "r"(b0), "r"(b1));
        }
    }
    __syncthreads();
  }

  if (Anext){
    #pragma unroll
    for (int fm=0; fm<4; fm++){
      #pragma unroll
      for (int fn=0; fn<4; fn++){
        int r0 = wm + fm*16 + (lane>>2);
        int c0 = wn + fn*8 + (lane&3)*2;
        float b0 = bias[bn + c0], b1 = bias[bn + c0 + 1];
        #pragma unroll
        for (int h=0; h<2; h++){
          int r = r0 + h*8;
          float v0 = fmaxf(acc[fm][fn][h*2+0] + b0, 0.f);
          float v1 = fmaxf(acc[fm][fn][h*2+1] + b1, 0.f);
          __half h0,l0,h1,l1;
          split_f16(v0,h0,l0); split_f16(v1,h1,l1);
          *(unsigned*)(sm + r*256 + c0*2)         = packh(h0,h1);
          *(unsigned*)(sm + 32768 + r*256 + c0*2) = packh(l0,l1);
        }
      }
    }
    __syncthreads();
    size_t rstride = 2*(size_t)Knext;
    #pragma unroll
    for (int seg=0; seg<2; seg++){
      int srcoff = seg*32768;
      size_t segoff = (size_t)seg*Knext;
      #pragma unroll
      for (int p=0; p<8; p++){
        int idx = p*256 + tid;
        int r = idx>>4, cb = (idx&15)*16;
        uint4 val = *(const uint4*)(sm + srcoff + r*256 + cb);
        *(uint4*)((char*)(Anext + (size_t)(bm+r)*rstride + segoff + bn) + cb) = val;
      }
    }
  } else {
    #pragma unroll
    for (int fm=0; fm<4; fm++){
      #pragma unroll
      for (int fn=0; fn<4; fn++){
        int r0 = wm + fm*16 + (lane>>2);
        int c0 = wn + fn*8 + (lane&3)*2;
        #pragma unroll
        for (int h=0; h<2; h++){
          int m = bm + r0 + h*8;
          int n0g = bn + c0;
          if (n0g   < Nfinal) Cfinal[(size_t)m*Nfinal + n0g  ] = acc[fm][fn][h*2+0] + bias[n0g];
          if (n0g+1 < Nfinal) Cfinal[(size_t)m*Nfinal + n0g+1] = acc[fm][fn][h*2+1] + bias[n0g+1];
        }
      }
    }
  }
  #undef MM_ISSUE
}

// ---- host launch ----
static void* sym_addr_(const void* s){ void* p=nullptr; cudaGetSymbolAddress(&p, s); return p; }

extern "C" void kernel_launch(void* const* d_in, const int* in_sizes, int n_in,
                              void* d_out, int out_size){
  const float* vertices = (const float*)d_in[0];
  const float* onehot   = (const float*)d_in[1];
  const float* d0       = (const float*)d_in[2];
  const float* W[8]; const float* Bb[8]; const float* DD[8];
  for (int i=1;i<=7;i++){
    W[i]  = (const float*)d_in[3*i];
    Bb[i] = (const float*)d_in[3*i+1];
    DD[i] = (const float*)d_in[3*i+2];
  }
  const float* cw1=(const float*)d_in[24]; const float* cb1=(const float*)d_in[25];
  const float* cw2=(const float*)d_in[26]; const float* cb2=(const float*)d_in[27];
  const float* cw3=(const float*)d_in[28]; const float* cb3=(const float*)d_in[29];
  float* out = (float*)d_out;

  int*   perm1=(int*)  sym_addr_(g_perm1); int*   perm2=(int*)  sym_addr_(g_perm2);
  int*   ni0  =(int*)  sym_addr_(g_ni0);   float* dn0  =(float*)sym_addr_(g_dn0);
  float* fmA  =(float*)sym_addr_(g_fmA);   float* ft   =(float*)sym_addr_(g_ft);
  float* v1   =(float*)sym_addr_(g_v1);
  int*   ni1  =(int*)  sym_addr_(g_ni1);   float* dn1  =(float*)sym_addr_(g_dn1);
  float* fmB  =(float*)sym_addr_(g_fmB);   float* v2   =(float*)sym_addr_(g_v2);
  int*   ni2  =(int*)  sym_addr_(g_ni2);   float* dn2  =(float*)sym_addr_(g_dn2);
  float* fmC  =(float*)sym_addr_(g_fmC);   float* fg   =(float*)sym_addr_(g_fglob);
  int*   n1   =(int*)  sym_addr_(g_n1);    int*   n2   =(int*)  sym_addr_(g_n2);
  __half* A1=(__half*)sym_addr_(g_A1);  __half* W1=(__half*)sym_addr_(g_W1);
  __half* A2=(__half*)sym_addr_(g_A2);  __half* W2=(__half*)sym_addr_(g_W2);
  __half* A3=(__half*)sym_addr_(g_A3);  __half* W3=(__half*)sym_addr_(g_W3);

  const float R2A = (float)(0.25*0.25);
  const float R2B = (float)(0.39*0.39);
  const float R2C = (float)(0.63*0.63);

  const int DSMEM = MM_STG*16384*2;   // 64KB
  cudaFuncSetAttribute(k_mm, cudaFuncAttributeMaxDynamicSharedMemorySize, DSMEM);

  k_perm<<<1,1024>>>();

  // Stage A (2048 pts) — ball fused with conv_surface
  k_ball   <<<dim3(N0/4,BSZ),128>>>(vertices, N0, R2A, ni0, dn0, d0, fmA, 96);
  k_linear <<<dim3(N0/4,BSZ),256>>>(fmA, 96, 32,  W[1], Bb[1], ft, N0);
  k_act    <<<dim3(N0/8,BSZ),256>>>(dn0, ni0, DD[1], ft, fmA, 96, 32, N0);
  k_linear <<<dim3(N0/4,BSZ),256>>>(fmA, 96, 64,  W[2], Bb[2], ft, N0);
  k_act    <<<dim3(N0/8,BSZ),256>>>(dn0, ni0, DD[2], ft, fmA, 96, 64, N0);
  k_pool   <<<dim3(N1,BSZ),128>>>(perm1, ni0, fmA, 96, 96, vertices, fmB, 192, v1, N0, N1);

  // Stage B (512 pts)
  k_ball   <<<dim3(N1/4,BSZ),128>>>(v1, N1, R2B, ni1, dn1, nullptr, nullptr, 0);
  k_linear <<<dim3(N1/4,BSZ),256>>>(fmB, 192, 96,  W[3], Bb[3], ft, N1);
  k_act    <<<dim3(N1/8,BSZ),256>>>(dn1, ni1, DD[3], ft, fmB, 192, 96, N1);
  k_linear <<<dim3(N1/4,BSZ),256>>>(fmB, 192, 128, W[4], Bb[4], ft, N1);
  k_act    <<<dim3(N1/8,BSZ),256>>>(dn1, ni1, DD[4], ft, fmB, 192, 128, N1);
  k_linear <<<dim3(N1/4,BSZ),256>>>(fmB, 192, 160, W[5], Bb[5], ft, N1);
  k_act    <<<dim3(N1/8,BSZ),256>>>(dn1, ni1, DD[5], ft, fmB, 192, 160, N1);
  k_pool   <<<dim3(N2,BSZ),128>>>(perm2, ni1, fmB, 192, 192, v1, fmC, 256, v2, N1, N2);

  // Stage C (128 pts)
  k_ball   <<<dim3(N2/4,BSZ),128>>>(v2, N2, R2C, ni2, dn2, nullptr, nullptr, 0);
  k_linear <<<dim3(N2/4,BSZ),256>>>(fmC, 256, 192, W[6], Bb[6], ft, N2);
  k_act    <<<dim3(N2/8,BSZ),256>>>(dn2, ni2, DD[6], ft, fmC, 256, 192, N2);
  k_linear <<<dim3(N2/4,BSZ),256>>>(fmC, 256, 224, W[7], Bb[7], ft, N2);
  k_act    <<<dim3(N2/8,BSZ),256>>>(dn2, ni2, DD[7], ft, fmC, 256, 224, N2);
  k_global <<<BSZ,256>>>(fmC, fg);

  // Fuse + head (split-fp16 mma.sync)
  k_nearest2  <<<dim3(N0/4,BSZ,2),128>>>(vertices, v1, v2, n1, n2);
  k_wsplit_all<<<(WT1+WT2+WT3+255)/256,256>>>(cw1, cw2, cw3, W1, W2, W3);
  k_fuse_split<<<dim3(N0,BSZ),256>>>(onehot, fmA, fmB, fmC, fg, n1, n2, A1);
  k_mm<<<dim3(8,128),256,DSMEM>>>(A1, W1, cb1, 2944, A2, 1024, nullptr, 0);
  k_mm<<<dim3(4,128),256,DSMEM>>>(A2, W2, cb2, 2048, A3,  512, nullptr, 0);
  k_mm<<<dim3(1,128),256,DSMEM>>>(A3, W3, cb3, 1024, nullptr, 0, out, 50);
}

// round 17
// speedup vs baseline: 1.1168x; 1.0216x over previous
#include <cuda_runtime.h>
#include <cuda_bf16.h>
#include <cuda_fp16.h>
#include <math.h>
#include <float.h>
#include <stdint.h>

#define BSZ 8
#define N0 2048
#define N1 512
#define N2 128

// Split-fp16 head GEMMs (mma.sync; K doubled, A'=[hi|lo], B'=[hi|hi]):
//   gemm1: M=16384, N=1024, K'=2944; gemm2: N=512, K'=2048; gemm3: N=128(pad 50), K'=1024

// ---- scratch (device globals; allocations are forbidden) ----
__device__ int   g_perm1[N0];
__device__ int   g_perm2[N1];
__device__ int   g_ni0[BSZ*N0*32];
__device__ float g_dn0[BSZ*N0*32*3];
__device__ float g_fmA[BSZ*N0*96];
__device__ float g_ft [BSZ*N0*64];
__device__ float g_v1 [BSZ*N1*3];
__device__ int   g_ni1[BSZ*N1*32];
__device__ float g_dn1[BSZ*N1*32*3];
__device__ float g_fmB[BSZ*N1*192];
__device__ float g_v2 [BSZ*N2*3];
__device__ int   g_ni2[BSZ*N2*32];
__device__ float g_dn2[BSZ*N2*32*3];
__device__ float g_fmC[BSZ*N2*256];
__device__ float g_fglob[BSZ*256];
__device__ int   g_n1[BSZ*N0];
__device__ int   g_n2[BSZ*N0];

__device__ __half g_A1[(size_t)16384*2944];
__device__ __half g_W1[(size_t)1024 *2944];
__device__ __half g_A2[(size_t)16384*2048];
__device__ __half g_W2[(size_t)512  *2048];
__device__ __half g_A3[(size_t)16384*1024];
__device__ __half g_W3[(size_t)128  *1024];

__device__ __forceinline__ uint32_t smem_u32(const void* p){
  uint32_t a;
  asm("{ .reg .u64 t; cvta.to.shared.u64 t, %1; cvt.u32.u64 %0, t; }" : "=r"(a) : "l"(p));
  return a;
}
__device__ __forceinline__ void split_f16(float v, __half& hi, __half& lo){
  hi = __float2half_rn(v);
  lo = __float2half_rn(v - __half2float(hi));
}
__device__ __forceinline__ unsigned packh(__half a, __half b){
  return (unsigned)__half_as_ushort(a) | ((unsigned)__half_as_ushort(b) << 16);
}

// ---- threefry2x32 (exact JAX cipher) ----
__device__ __forceinline__ void tfry(unsigned k0, unsigned k1, unsigned &x0, unsigned &x1){
  unsigned ks2 = k0 ^ k1 ^ 0x1BD11BDAu;
  x0 += k0; x1 += k1;
#define TF_R(r) { x0 += x1; x1 = (x1<<(r))|(x1>>(32-(r))); x1 ^= x0; }
  TF_R(13) TF_R(15) TF_R(26) TF_R(6)   x0 += k1;  x1 += ks2 + 1u;
  TF_R(17) TF_R(29) TF_R(16) TF_R(24)  x0 += ks2; x1 += k0  + 2u;
  TF_R(13) TF_R(15) TF_R(26) TF_R(6)   x0 += k0;  x1 += k1  + 3u;
  TF_R(17) TF_R(29) TF_R(16) TF_R(24)  x0 += k1;  x1 += ks2 + 4u;
  TF_R(13) TF_R(15) TF_R(26) TF_R(6)   x0 += ks2; x1 += k0  + 5u;
#undef TF_R
}
__device__ __forceinline__ void tfry2(unsigned k0, unsigned k1, unsigned c0, unsigned c1,
                                      unsigned &o0, unsigned &o1){
  o0 = c0; o1 = c1; tfry(k0, k1, o0, o1);
}

__device__ void bitonic_sort(unsigned long long* sk, int* sv, int n, int tid, int nthr){
  for (int k=2;k<=n;k<<=1){
    for (int j=k>>1;j>0;j>>=1){
      for (int i=tid;i<n;i+=nthr){
        int ix=i^j;
        if (ix>i){
          bool up = ((i & k)==0);
          unsigned long long a=sk[i], c=sk[ix];
          if ((a>c)==up){
            sk[i]=c; sk[ix]=a;
            int t=sv[i]; sv[i]=sv[ix]; sv[ix]=t;
          }
        }
      }
      __syncthreads();
    }
  }
}

// jax.random.permutation, PARTITIONABLE threefry (modern JAX default)
__global__ void k_perm(){
  __shared__ unsigned long long sk[2048];
  __shared__ int sv[2048];
  int tid = threadIdx.x;   // 1024

  unsigned ck0, ck1; tfry2(0u, 42u, 0u, 1u, ck0, ck1);   // fold_in(key(42),1)
  for (int round=0; round<2; round++){
    unsigned nk0, nk1; tfry2(ck0, ck1, 0u, 0u, nk0, nk1);
    unsigned s0,  s1;  tfry2(ck0, ck1, 0u, 1u, s0,  s1);
    unsigned a0,a1; tfry2(s0, s1, 0u, (unsigned)tid,        a0, a1);
    unsigned b0,b1; tfry2(s0, s1, 0u, (unsigned)(tid+1024), b0, b1);
    unsigned bitsA = a0 ^ a1, bitsB = b0 ^ b1;
    if (round==0){ sv[tid]=tid; sv[tid+1024]=tid+1024; }
    __syncthreads();
    sk[tid]      = ((unsigned long long)bitsA<<32) | (unsigned)tid;
    sk[tid+1024] = ((unsigned long long)bitsB<<32) | (unsigned)(tid+1024);
    __syncthreads();
    bitonic_sort(sk, sv, 2048, tid, 1024);
    ck0=nk0; ck1=nk1;
  }
  g_perm1[tid]      = sv[tid];
  g_perm1[tid+1024] = sv[tid+1024];
  __syncthreads();

  unsigned f0, f1; tfry2(0u, 42u, 0u, 2u, f0, f1);        // fold_in(key(42),2)
  unsigned s0, s1; tfry2(f0, f1, 0u, 1u, s0, s1);
  if (tid < 512){
    unsigned a0,a1; tfry2(s0, s1, 0u, (unsigned)tid, a0, a1);
    sk[tid] = ((unsigned long long)(a0^a1)<<32) | (unsigned)tid;
    sv[tid] = tid;
  }
  __syncthreads();
  bitonic_sort(sk, sv, 512, tid, 1024);
  if (tid<512) g_perm2[tid]=sv[tid];
}

// ---- ball query; optionally fused conv_surface (stage A: fm0 != nullptr) ----
__global__ void k_ball(const float* __restrict__ verts, int Nv, float r2,
                       int* __restrict__ ni, float* __restrict__ dn,
                       const float* __restrict__ d0, float* __restrict__ fm0, int ldOut){
  __shared__ int sidx[4][32];
  __shared__ float sdn[4][32][3];
  int b = blockIdx.y;
  int w = threadIdx.x>>5, lane = threadIdx.x&31;
  int v = blockIdx.x*4 + w;
  const float* vb = verts + (size_t)b*Nv*3;
  float cx = vb[v*3+0], cy = vb[v*3+1], cz = vb[v*3+2];
  int cnt = 0;
  for (int base=0; base<Nv && cnt<32; base+=32){
    int j = base + lane;
    float dx = __fsub_rn(cx, vb[j*3+0]);
    float dy = __fsub_rn(cy, vb[j*3+1]);
    float dz = __fsub_rn(cz, vb[j*3+2]);
    float sq = __fadd_rn(__fadd_rn(__fmul_rn(dx,dx),__fmul_rn(dy,dy)),__fmul_rn(dz,dz));
    unsigned m = __ballot_sync(0xffffffffu, !(sq > r2));
    while (m && cnt<32){
      int l = __ffs(m)-1; m &= m-1u;
      if (lane==0) sidx[w][cnt] = base + l;
      cnt++;
    }
  }
  __syncwarp();
  int first = sidx[w][0];
  int idx = (lane<cnt) ? sidx[w][lane] : first;
  ni[((size_t)(b*Nv)+v)*32 + lane] = idx;
  float nx = __fsub_rn(vb[idx*3+0], cx);
  float ny = __fsub_rn(vb[idx*3+1], cy);
  float nz = __fsub_rn(vb[idx*3+2], cz);
  float nrm = sqrtf(nx*nx + ny*ny + nz*nz);
  float den = fmaxf(nrm, 1e-12f);
  float d0v = nx/den, d1v = ny/den, d2v = nz/den;
  float* dp = dn + (((size_t)(b*Nv)+v)*32 + lane)*3;
  dp[0]=d0v; dp[1]=d1v; dp[2]=d2v;

  if (fm0){
    sdn[w][lane][0]=d0v; sdn[w][lane][1]=d1v; sdn[w][lane][2]=d2v;
    __syncwarp();
    float u0=d0[lane], u1=d0[32+lane], u2=d0[64+lane];
    float dnm = fmaxf(sqrtf(u0*u0+u1*u1+u2*u2), 1e-12f);
    u0/=dnm; u1/=dnm; u2/=dnm;
    float m = 0.f;
    #pragma unroll 4
    for (int n=0;n<32;n++){
      float t = sdn[w][n][0]*u0 + sdn[w][n][1]*u1 + sdn[w][n][2]*u2;
      m = fmaxf(m, t);
    }
    fm0[((size_t)(b*Nv)+v)*ldOut + lane] = m;
  }
}

// ---- linear (R13 version): 4 vertices/block, 256 threads ----
__global__ void k_linear(const float* __restrict__ fm, int ld, int Cin,
                         const float* __restrict__ w, const float* __restrict__ bias,
                         float* __restrict__ ft, int Nv){
  __shared__ float sf[4][224];
  int b = blockIdx.y;
  int v0 = blockIdx.x*4;
  int tid = threadIdx.x;   // 256
  for (int idx=tid; idx<4*Cin; idx+=256){
    int vl = idx / Cin, c = idx % Cin;
    sf[vl][c] = fm[((size_t)(b*Nv) + v0+vl)*ld + c];
  }
  __syncthreads();
  int o = tid & 63, vl = tid >> 6;
  float acc = bias[o];
  for (int c=0;c<Cin;c++) acc += sf[vl][c] * w[c*64+o];
  ft[((size_t)(b*Nv) + v0+vl)*64 + o] = acc;
}

// ---- conv act: lane-preload + shfl broadcast, dual fmax chains (order-safe) ----
__global__ void k_act(const float* __restrict__ dn, const int* __restrict__ ni,
                      const float* __restrict__ dd, const float* __restrict__ ft,
                      float* __restrict__ fmOut, int ldOut, int Coff, int Nv){
  int b = blockIdx.y;
  int w = threadIdx.x>>5, lane = threadIdx.x&31;
  int v = blockIdx.x*8 + w;
  float u0=dd[lane], u1=dd[32+lane], u2=dd[64+lane];
  float den = fmaxf(sqrtf(u0*u0+u1*u1+u2*u2), 1e-12f);
  u0/=den; u1/=den; u2/=den;
  const float* dp  = dn + ((size_t)(b*Nv)+v)*96;
  const int*   nip = ni + ((size_t)(b*Nv)+v)*32;
  const float* ftb = ft + (size_t)b*Nv*64;
  // lane-parallel preload of this vertex's 32 neighbors + direction triples
  int   nbR = nip[lane];
  float d0R = dp[lane*3+0], d1R = dp[lane*3+1], d2R = dp[lane*3+2];
  float center = ftb[(size_t)v*64 + lane];
  float actA = -FLT_MAX, actB = -FLT_MAX;
  #pragma unroll
  for (int n=0;n<32;n+=2){
    int nb0 = __shfl_sync(0xffffffffu, nbR, n);
    int nb1 = __shfl_sync(0xffffffffu, nbR, n+1);
    float s0 = ftb[(size_t)nb0*64 + 32 + lane];
    float s1 = ftb[(size_t)nb1*64 + 32 + lane];
    float e0 = __shfl_sync(0xffffffffu, d0R, n);
    float e1 = __shfl_sync(0xffffffffu, d1R, n);
    float e2 = __shfl_sync(0xffffffffu, d2R, n);
    float f0 = __shfl_sync(0xffffffffu, d0R, n+1);
    float f1 = __shfl_sync(0xffffffffu, d1R, n+1);
    float f2 = __shfl_sync(0xffffffffu, d2R, n+1);
    float t0 = fmaxf(e0*u0 + e1*u1 + e2*u2, 0.f);
    float t1 = fmaxf(f0*u0 + f1*u1 + f2*u2, 0.f);
    actA = fmaxf(actA, t0*s0);
    actB = fmaxf(actB, t1*s1);
  }
  float act = fmaxf(actA, actB);
  fmOut[((size_t)(b*Nv)+v)*ldOut + Coff + lane] = fmaxf(center + act, 0.f);
}

__global__ void k_pool(const int* __restrict__ perm, const int* __restrict__ ni,
                       const float* __restrict__ fmIn, int ldIn, int C,
                       const float* __restrict__ vin, float* __restrict__ fmOut, int ldOut,
                       float* __restrict__ vout, int Nin, int Nout){
  int b = blockIdx.y, p = blockIdx.x;
  int v = perm[p];
  const int* nip = ni + ((size_t)(b*Nin)+v)*32;
  int j0=nip[0], j1=nip[1], j2=nip[2], j3=nip[3];
  const float* base = fmIn + (size_t)b*Nin*ldIn;
  for (int c=threadIdx.x; c<C; c+=blockDim.x){
    float m = fmaxf(fmaxf(base[(size_t)j0*ldIn+c], base[(size_t)j1*ldIn+c]),
                    fmaxf(base[(size_t)j2*ldIn+c], base[(size_t)j3*ldIn+c]));
    fmOut[((size_t)(b*Nout)+p)*ldOut + c] = m;
  }
  if (threadIdx.x<3)
    vout[((size_t)(b*Nout)+p)*3+threadIdx.x] = vin[((size_t)(b*Nin)+v)*3+threadIdx.x];
}

__global__ void k_global(const float* __restrict__ fmC, float* __restrict__ fg){
  int b = blockIdx.x, c = threadIdx.x;
  float m = -FLT_MAX;
  for (int v=0; v<N2; v++) m = fmaxf(m, fmC[((size_t)(b*N2)+v)*256 + c]);
  fg[b*256+c] = m;
}

// ---- nearest (both targets in one launch; z=0 -> v1/n1, z=1 -> v2/n2) ----
__global__ void k_nearest2(const float* __restrict__ q, const float* __restrict__ src1,
                           const float* __restrict__ src2, int* __restrict__ out1,
                           int* __restrict__ out2){
  int b = blockIdx.y;
  int w = threadIdx.x>>5, lane = threadIdx.x&31;
  int v = blockIdx.x*4 + w;
  const float* src = blockIdx.z ? src2 : src1;
  int Nsrc = blockIdx.z ? N2 : N1;
  int* out = blockIdx.z ? out2 : out1;
  const float* qp = q + ((size_t)(b*N0)+v)*3;
  float qx=qp[0], qy=qp[1], qz=qp[2];
  float best = FLT_MAX; int bi = 0x7fffffff;
  for (int j=lane; j<Nsrc; j+=32){
    const float* s = src + ((size_t)(b*Nsrc)+j)*3;
    float dx=__fsub_rn(qx,s[0]), dy=__fsub_rn(qy,s[1]), dz=__fsub_rn(qz,s[2]);
    float sq=__fadd_rn(__fadd_rn(__fmul_rn(dx,dx),__fmul_rn(dy,dy)),__fmul_rn(dz,dz));
    if (sq < best){ best=sq; bi=j; }
  }
  for (int off=16; off; off>>=1){
    float ob = __shfl_down_sync(0xffffffffu, best, off);
    int   oi = __shfl_down_sync(0xffffffffu, bi,   off);
    if (ob < best || (ob==best && oi<bi)){ best=ob; bi=oi; }
  }
  if (lane==0) out[(size_t)b*N0+v] = bi;
}

// ---- fuse -> split-fp16 A1 [16384][2944] = [hi(1472)|lo]; packed 4B stores ----
__device__ __forceinline__ float fuse_fetch(int c, const float* fa, const float* fb,
                                            const float* fc, const float* fg,
                                            const float* onehot, int b){
  if (c>=1424) return 0.f;
  if      (c<32)   return fa[c];
  else if (c<96)   return fa[c-32];
  else if (c<192)  return fa[c-96];
  else if (c<320)  return fb[c-192];
  else if (c<480)  return fb[c-320];
  else if (c<672)  return fb[c-480];
  else if (c<896)  return fc[c-672];
  else if (c<1152) return fc[c-896];
  else if (c<1408) return fg[b*256 + (c-1152)];
  else             return onehot[b*16 + (c-1408)];
}

__global__ void k_fuse_split(const float* __restrict__ onehot, const float* __restrict__ fmA,
                             const float* __restrict__ fmB, const float* __restrict__ fmC,
                             const float* __restrict__ fg, const int* __restrict__ n1,
                             const int* __restrict__ n2, __half* __restrict__ A1){
  int b = blockIdx.y, v = blockIdx.x;
  int i1 = n1[b*N0+v], i2 = n2[b*N0+v];
  const float* fa = fmA + ((size_t)(b*N0)+v )*96;
  const float* fb = fmB + ((size_t)(b*N1)+i1)*192;
  const float* fc = fmC + ((size_t)(b*N2)+i2)*256;
  size_t row = (size_t)(b*N0 + v) * 2944;
  for (int c2=threadIdx.x; c2<736; c2+=256){
    int c = c2*2;
    float x0 = fuse_fetch(c,   fa, fb, fc, fg, onehot, b);
    float x1 = fuse_fetch(c+1, fa, fb, fc, fg, onehot, b);
    __half h0,l0,h1,l1;
    split_f16(x0,h0,l0); split_f16(x1,h1,l1);
    *(unsigned*)&A1[row + c]        = packh(h0,h1);
    *(unsigned*)&A1[row + 1472 + c] = packh(l0,l1);
  }
}

// ---- all three weight splits in one launch: [hi | hi] per row; zero-pads ----
#define WT1 (1024*1472)
#define WT2 (512*1024)
#define WT3 (128*512)
__global__ void k_wsplit_all(const float* __restrict__ w1, const float* __restrict__ w2,
                             const float* __restrict__ w3, __half* __restrict__ o1,
                             __half* __restrict__ o2, __half* __restrict__ o3){
  int idx = blockIdx.x*256 + threadIdx.x;
  const float* w; __half* out; int N, K, Kpad;
  if (idx < WT1){ w=w1; out=o1; N=1024; K=1424; Kpad=1472; }
  else if (idx < WT1+WT2){ idx-=WT1; w=w2; out=o2; N=512; K=1024; Kpad=1024; }
  else if (idx < WT1+WT2+WT3){ idx-=WT1+WT2; w=w3; out=o3; N=50; K=512; Kpad=512; }
  else return;
  int n = idx / Kpad, c = idx - n*Kpad;
  float v = (n < N && c < K) ? w[(size_t)n*K + c] : 0.f;
  __half hi = __float2half_rn(v);
  size_t base = (size_t)n * 2 * Kpad;
  out[base + c]        = hi;
  out[base + Kpad + c] = hi;
}

// ---- fp16 mma.sync GEMM (R13 baseline): BM=BN=128, BK=64, 2-stage, 2 CTAs/SM ----
#define MM_STG 2
__global__ void __launch_bounds__(256, 2)
k_mm(const __half* __restrict__ A, const __half* __restrict__ B,
     const float* __restrict__ bias, int K,
     __half* __restrict__ Anext, int Knext,
     float* __restrict__ Cfinal, int Nfinal)
{
  extern __shared__ char sm[];
  int tid = threadIdx.x, lane = tid&31, wid = tid>>5;
  int bn = blockIdx.x*128, bm = blockIdx.y*128;
  int wm = (wid>>2)*64, wn = (wid&3)*32;
  int nK = K >> 6;
  uint32_t sA0 = smem_u32(sm);
  uint32_t sB0 = sA0 + MM_STG*16384;

  float acc[4][4][4];
  #pragma unroll
  for (int i=0;i<4;i++)
    #pragma unroll
    for (int j=0;j<4;j++)
      #pragma unroll
      for (int q=0;q<4;q++) acc[i][j][q]=0.f;

  #define MM_ISSUE(KT) do{ \
    int _s = (KT) % MM_STG; \
    _Pragma("unroll") \
    for (int it=0; it<4; it++){ \
      int idx = it*256 + tid; \
      int r = idx>>3, c = idx&7; \
      uint32_t sw = ((uint32_t)(c ^ (r&7)))<<4; \
      uint32_t sa = sA0 + _s*16384 + r*128 + sw; \
      const void* ga = A + (size_t)(bm+r)*K + (KT)*64 + c*8; \
      asm volatile("cp.async.cg.shared.global [%0], [%1], 16;" :: "r"(sa), "l"(ga)); \
      uint32_t sb = sB0 + _s*16384 + r*128 + sw; \
      const void* gb = B + (size_t)(bn+r)*K + (KT)*64 + c*8; \
      asm volatile("cp.async.cg.shared.global [%0], [%1], 16;" :: "r"(sb), "l"(gb)); \
    } \
    asm volatile("cp.async.commit_group;" ::: "memory"); \
  } while(0)

  MM_ISSUE(0);

  for (int kt=0; kt<nK; kt++){
    int s = kt % MM_STG;
    asm volatile("cp.async.wait_group 0;" ::: "memory");
    __syncthreads();
    if (kt+1 < nK) MM_ISSUE(kt+1);
    uint32_t ab = sA0 + s*16384;
    uint32_t bb = sB0 + s*16384;
    #pragma unroll
    for (int kk=0; kk<4; kk++){
      uint32_t af[4][4], bfr[2][4];
      #pragma unroll
      for (int fm=0; fm<4; fm++){
        int row = wm + fm*16 + (lane&15);
        int ch  = kk*2 + (lane>>4);
        uint32_t ad = ab + row*128 + ((uint32_t)(ch ^ (row&7))<<4);
        asm volatile("ldmatrix.sync.aligned.m8n8.x4.shared.b16 {%0,%1,%2,%3}, [%4];"
          : "=r"(af[fm][0]),"=r"(af[fm][1]),"=r"(af[fm][2]),"=r"(af[fm][3]) : "r"(ad));
      }
      #pragma unroll
      for (int fp=0; fp<2; fp++){
        int row = wn + fp*16 + ((lane>>4)&1)*8 + (lane&7);
        int ch  = kk*2 + ((lane>>3)&1);
        uint32_t bd = bb + row*128 + ((uint32_t)(ch ^ (row&7))<<4);
        asm volatile("ldmatrix.sync.aligned.m8n8.x4.shared.b16 {%0,%1,%2,%3}, [%4];"
          : "=r"(bfr[fp][0]),"=r"(bfr[fp][1]),"=r"(bfr[fp][2]),"=r"(bfr[fp][3]) : "r"(bd));
      }
      #pragma unroll
      for (int fm=0; fm<4; fm++)
        #pragma unroll
        for (int fn=0; fn<4; fn++){
          uint32_t b0 = bfr[fn>>1][(fn&1)*2], b1 = bfr[fn>>1][(fn&1)*2+1];
          asm volatile("mma.sync.aligned.m16n8k16.row.col.f32.f16.f16.f32 "
            "{%0,%1,%2,%3}, {%4,%5,%6,%7}, {%8,%9}, {%0,%1,%2,%3};"
            : "+f"(acc[fm][fn][0]), "+f"(acc[fm][fn][1]), "+f"(acc[fm][fn][2]), "+f"(acc[fm][fn][3])
            : "r"(af[fm][0]), "r"(af[fm][1]), "r"(af[fm][2]), "r"(af[fm][3]), "r"(b0), "r"(b1));
        }
    }
    __syncthreads();
  }

  if (Anext){
    #pragma unroll
    for (int fm=0; fm<4; fm++){
      #pragma unroll
      for (int fn=0; fn<4; fn++){
        int r0 = wm + fm*16 + (lane>>2);
        int c0 = wn + fn*8 + (lane&3)*2;
        float b0 = bias[bn + c0], b1 = bias[bn + c0 + 1];
        #pragma unroll
        for (int h=0; h<2; h++){
          int r = r0 + h*8;
          float v0 = fmaxf(acc[fm][fn][h*2+0] + b0, 0.f);
          float v1 = fmaxf(acc[fm][fn][h*2+1] + b1, 0.f);
          __half h0,l0,h1,l1;
          split_f16(v0,h0,l0); split_f16(v1,h1,l1);
          *(unsigned*)(sm + r*256 + c0*2)         = packh(h0,h1);
          *(unsigned*)(sm + 32768 + r*256 + c0*2) = packh(l0,l1);
        }
      }
    }
    __syncthreads();
    size_t rstride = 2*(size_t)Knext;
    #pragma unroll
    for (int seg=0; seg<2; seg++){
      int srcoff = seg*32768;
      size_t segoff = (size_t)seg*Knext;
      #pragma unroll
      for (int p=0; p<8; p++){
        int idx = p*256 + tid;
        int r = idx>>4, cb = (idx&15)*16;
        uint4 val = *(const uint4*)(sm + srcoff + r*256 + cb);
        *(uint4*)((char*)(Anext + (size_t)(bm+r)*rstride + segoff + bn) + cb) = val;
      }
    }
  } else {
    #pragma unroll
    for (int fm=0; fm<4; fm++){
      #pragma unroll
      for (int fn=0; fn<4; fn++){
        int r0 = wm + fm*16 + (lane>>2);
        int c0 = wn + fn*8 + (lane&3)*2;
        #pragma unroll
        for (int h=0; h<2; h++){
          int m = bm + r0 + h*8;
          int n0g = bn + c0;
          if (n0g   < Nfinal) Cfinal[(size_t)m*Nfinal + n0g  ] = acc[fm][fn][h*2+0] + bias[n0g];
          if (n0g+1 < Nfinal) Cfinal[(size_t)m*Nfinal + n0g+1] = acc[fm][fn][h*2+1] + bias[n0g+1];
        }
      }
    }
  }
  #undef MM_ISSUE
}

// ---- host launch ----
static void* sym_addr_(const void* s){ void* p=nullptr; cudaGetSymbolAddress(&p, s); return p; }

extern "C" void kernel_launch(void* const* d_in, const int* in_sizes, int n_in,
                              void* d_out, int out_size){
  const float* vertices = (const float*)d_in[0];
  const float* onehot   = (const float*)d_in[1];
  const float* d0       = (const float*)d_in[2];
  const float* W[8]; const float* Bb[8]; const float* DD[8];
  for (int i=1;i<=7;i++){
    W[i]  = (const float*)d_in[3*i];
    Bb[i] = (const float*)d_in[3*i+1];
    DD[i] = (const float*)d_in[3*i+2];
  }
  const float* cw1=(const float*)d_in[24]; const float* cb1=(const float*)d_in[25];
  const float* cw2=(const float*)d_in[26]; const float* cb2=(const float*)d_in[27];
  const float* cw3=(const float*)d_in[28]; const float* cb3=(const float*)d_in[29];
  float* out = (float*)d_out;

  int*   perm1=(int*)  sym_addr_(g_perm1); int*   perm2=(int*)  sym_addr_(g_perm2);
  int*   ni0  =(int*)  sym_addr_(g_ni0);   float* dn0  =(float*)sym_addr_(g_dn0);
  float* fmA  =(float*)sym_addr_(g_fmA);   float* ft   =(float*)sym_addr_(g_ft);
  float* v1   =(float*)sym_addr_(g_v1);
  int*   ni1  =(int*)  sym_addr_(g_ni1);   float* dn1  =(float*)sym_addr_(g_dn1);
  float* fmB  =(float*)sym_addr_(g_fmB);   float* v2   =(float*)sym_addr_(g_v2);
  int*   ni2  =(int*)  sym_addr_(g_ni2);   float* dn2  =(float*)sym_addr_(g_dn2);
  float* fmC  =(float*)sym_addr_(g_fmC);   float* fg   =(float*)sym_addr_(g_fglob);
  int*   n1   =(int*)  sym_addr_(g_n1);    int*   n2   =(int*)  sym_addr_(g_n2);
  __half* A1=(__half*)sym_addr_(g_A1);  __half* W1=(__half*)sym_addr_(g_W1);
  __half* A2=(__half*)sym_addr_(g_A2);  __half* W2=(__half*)sym_addr_(g_W2);
  __half* A3=(__half*)sym_addr_(g_A3);  __half* W3=(__half*)sym_addr_(g_W3);

  const float R2A = (float)(0.25*0.25);
  const float R2B = (float)(0.39*0.39);
  const float R2C = (float)(0.63*0.63);

  const int DSMEM = MM_STG*16384*2;   // 64KB
  cudaFuncSetAttribute(k_mm, cudaFuncAttributeMaxDynamicSharedMemorySize, DSMEM);

  k_perm<<<1,1024>>>();

  // Stage A (2048 pts) — ball fused with conv_surface
  k_ball   <<<dim3(N0/4,BSZ),128>>>(vertices, N0, R2A, ni0, dn0, d0, fmA, 96);
  k_linear <<<dim3(N0/4,BSZ),256>>>(fmA, 96, 32,  W[1], Bb[1], ft, N0);
  k_act    <<<dim3(N0/8,BSZ),256>>>(dn0, ni0, DD[1], ft, fmA, 96, 32, N0);
  k_linear <<<dim3(N0/4,BSZ),256>>>(fmA, 96, 64,  W[2], Bb[2], ft, N0);
  k_act    <<<dim3(N0/8,BSZ),256>>>(dn0, ni0, DD[2], ft, fmA, 96, 64, N0);
  k_pool   <<<dim3(N1,BSZ),128>>>(perm1, ni0, fmA, 96, 96, vertices, fmB, 192, v1, N0, N1);

  // Stage B (512 pts)
  k_ball   <<<dim3(N1/4,BSZ),128>>>(v1, N1, R2B, ni1, dn1, nullptr, nullptr, 0);
  k_linear <<<dim3(N1/4,BSZ),256>>>(fmB, 192, 96,  W[3], Bb[3], ft, N1);
  k_act    <<<dim3(N1/8,BSZ),256>>>(dn1, ni1, DD[3], ft, fmB, 192, 96, N1);
  k_linear <<<dim3(N1/4,BSZ),256>>>(fmB, 192, 128, W[4], Bb[4], ft, N1);
  k_act    <<<dim3(N1/8,BSZ),256>>>(dn1, ni1, DD[4], ft, fmB, 192, 128, N1);
  k_linear <<<dim3(N1/4,BSZ),256>>>(fmB, 192, 160, W[5], Bb[5], ft, N1);
  k_act    <<<dim3(N1/8,BSZ),256>>>(dn1, ni1, DD[5], ft, fmB, 192, 160, N1);
  k_pool   <<<dim3(N2,BSZ),128>>>(perm2, ni1, fmB, 192, 192, v1, fmC, 256, v2, N1, N2);

  // Stage C (128 pts)
  k_ball   <<<dim3(N2/4,BSZ),128>>>(v2, N2, R2C, ni2, dn2, nullptr, nullptr, 0);
  k_linear <<<dim3(N2/4,BSZ),256>>>(fmC, 256, 192, W[6], Bb[6], ft, N2);
  k_act    <<<dim3(N2/8,BSZ),256>>>(dn2, ni2, DD[6], ft, fmC, 256, 192, N2);
  k_linear <<<dim3(N2/4,BSZ),256>>>(fmC, 256, 224, W[7], Bb[7], ft, N2);
  k_act    <<<dim3(N2/8,BSZ),256>>>(dn2, ni2, DD[7], ft, fmC, 256, 224, N2);
  k_global <<<BSZ,256>>>(fmC, fg);

  // Fuse + head (split-fp16 mma.sync)
  k_nearest2  <<<dim3(N0/4,BSZ,2),128>>>(vertices, v1, v2, n1, n2);
  k_wsplit_all<<<(WT1+WT2+WT3+255)/256,256>>>(cw1, cw2, cw3, W1, W2, W3);
  k_fuse_split<<<dim3(N0,BSZ),256>>>(onehot, fmA, fmB, fmC, fg, n1, n2, A1);
  k_mm<<<dim3(8,128),256,DSMEM>>>(A1, W1, cb1, 2944, A2, 1024, nullptr, 0);
  k_mm<<<dim3(4,128),256,DSMEM>>>(A2, W2, cb2, 2048, A3,  512, nullptr, 0);
  k_mm<<<dim3(1,128),256,DSMEM>>>(A3, W3, cb3, 1024, nullptr, 0, out, 50);
}